// round 12
// baseline (speedup 1.0000x reference)
#include <cuda_runtime.h>
#include <cstdint>
#include <math.h>

// Problem constants
#define BB   4
#define CC   256
#define CQK  32
#define NNp  4096

// ---------------- scratch ----------------
__device__ float  g_q [(size_t)BB * NNp * CQK];   // [b][m][32]  K-major, tf32, *log2e
__device__ float  g_k [(size_t)BB * NNp * CQK];   // [b][n][32]  K-major, tf32
__device__ float  g_v [(size_t)BB * CC * NNp];    // [b][c][n]   tf32
__device__ float  g_o [(size_t)BB * NNp * CC];    // [b][m][c]   tf32
__device__ float  g_xT[(size_t)BB * NNp * CC];    // [b][m][c]   tf32
__device__ float  g_wv[(size_t)CC * CC];
__device__ float  g_wo[(size_t)CC * 2 * CC];

// ---------------- helpers ----------------
__device__ __forceinline__ float tf32r(float x) {
    uint32_t y;
    asm("cvt.rna.tf32.f32 %0, %1;" : "=r"(y) : "f"(x));
    return __uint_as_float(y);
}

__device__ __forceinline__ float ex2f(float x) {
    float y;
    asm("ex2.approx.f32 %0, %1;" : "=f"(y) : "f"(x));
    return y;
}

__device__ __forceinline__ uint32_t smem_u32(const void* p) {
    uint32_t a;
    asm("{ .reg .u64 t; cvta.to.shared.u64 t, %1; cvt.u32.u64 %0, t; }"
        : "=r"(a) : "l"(p));
    return a;
}

#define CP_ASYNC16(dst, src) \
    asm volatile("cp.async.cg.shared.global [%0], [%1], 16;" :: "r"(dst), "l"(src))
#define CP_COMMIT() asm volatile("cp.async.commit_group;" ::: "memory")
#define CP_WAIT(n)  asm volatile("cp.async.wait_group %0;" :: "n"(n) : "memory")

__device__ __forceinline__ void mma_tf32(float* d, const uint32_t* a, const uint32_t* b) {
    asm volatile(
        "mma.sync.aligned.m16n8k8.row.col.f32.tf32.tf32.f32 "
        "{%0,%1,%2,%3}, {%4,%5,%6,%7}, {%8,%9}, {%0,%1,%2,%3};"
        : "+f"(d[0]), "+f"(d[1]), "+f"(d[2]), "+f"(d[3])
        : "r"(a[0]), "r"(a[1]), "r"(a[2]), "r"(a[3]), "r"(b[0]), "r"(b[1]));
}

__device__ __forceinline__ void lda_frag(uint32_t* a, const float* p, int str) {
    a[0] = __float_as_uint(p[0]);
    a[1] = __float_as_uint(p[8 * str]);
    a[2] = __float_as_uint(p[4]);
    a[3] = __float_as_uint(p[8 * str + 4]);
}
__device__ __forceinline__ void ldb_frag(uint32_t* bf, const float* p) {
    bf[0] = __float_as_uint(p[0]);
    bf[1] = __float_as_uint(p[4]);
}

// ---------------- tf32 mma.sync GEMM (proven R10 version) ----------------
#define SROW 36
#define TILE_F (128 * SROW)

__global__ void __launch_bounds__(256, 2) tc_gemm(
    const float* __restrict__ A, int lda, size_t sAb,
    const float* __restrict__ B1, int ldb1, size_t sB1b,
    const float* __restrict__ B2, int ldb2, size_t sB2b, int ksplit,
    float* __restrict__ C, int ldc, size_t sCb,
    const float* __restrict__ bias, int K, int round_out)
{
    extern __shared__ float4 smem4[];
    float* sm = (float*)smem4;

    const int b = blockIdx.z;
    A  += (size_t)b * sAb;
    B1 += (size_t)b * sB1b;
    const float* B2p = B2 ? (B2 + (size_t)b * sB2b) : nullptr;
    C  += (size_t)b * sCb;

    const int n0 = blockIdx.x * 128;
    const int m0 = blockIdx.y * 128;
    const int t    = threadIdx.x;
    const int lane = t & 31;
    const int warp = t >> 5;
    const int wm = (warp & 3) * 32;
    const int wn = (warp >> 2) * 64;
    const int gr = lane >> 2;
    const int gc = lane & 3;

    const uint32_t sbase = smem_u32(sm);
    const int ldr = t >> 3;
    const int ldc4 = (t & 7) * 4;

    const int nk = K / 32;

    auto issue_tile = [&](int kb, int buf) {
        const int k0 = kb * 32;
        {
            const float* src = A + (size_t)(m0 + ldr) * lda + k0 + ldc4;
            uint32_t dst = sbase + (uint32_t)(buf * 2 * TILE_F) * 4u
                         + (uint32_t)(ldr * SROW + ldc4) * 4u;
#pragma unroll
            for (int i = 0; i < 4; i++)
                CP_ASYNC16(dst + (uint32_t)(i * 32 * SROW) * 4u,
                           src + (size_t)(i * 32) * lda);
        }
        {
            const float* Bp; int ldb, kk;
            if (k0 < ksplit) { Bp = B1;  ldb = ldb1; kk = k0; }
            else             { Bp = B2p; ldb = ldb2; kk = k0 - ksplit; }
            const float* src = Bp + (size_t)(n0 + ldr) * ldb + kk + ldc4;
            uint32_t dst = sbase + (uint32_t)((buf * 2 + 1) * TILE_F) * 4u
                         + (uint32_t)(ldr * SROW + ldc4) * 4u;
#pragma unroll
            for (int i = 0; i < 4; i++)
                CP_ASYNC16(dst + (uint32_t)(i * 32 * SROW) * 4u,
                           src + (size_t)(i * 32) * ldb);
        }
        CP_COMMIT();
    };

    float acc[2][8][4];
#pragma unroll
    for (int mf = 0; mf < 2; mf++)
#pragma unroll
        for (int nf = 0; nf < 8; nf++)
#pragma unroll
            for (int j = 0; j < 4; j++) acc[mf][nf][j] = 0.f;

    issue_tile(0, 0);

    for (int kb = 0; kb < nk; kb++) {
        const int buf = kb & 1;
        if (kb + 1 < nk) { issue_tile(kb + 1, buf ^ 1); CP_WAIT(1); }
        else             { CP_WAIT(0); }
        __syncthreads();

        const float* sA = sm + buf * 2 * TILE_F;
        const float* sB = sA + TILE_F;
#pragma unroll
        for (int ks = 0; ks < 4; ks++) {
            const int k0 = ks * 8;
            uint32_t afr[2][4], bfr[8][2];
#pragma unroll
            for (int mf = 0; mf < 2; mf++)
                lda_frag(afr[mf], sA + (wm + mf * 16 + gr) * SROW + k0 + gc, SROW);
#pragma unroll
            for (int nf = 0; nf < 8; nf++)
                ldb_frag(bfr[nf], sB + (wn + nf * 8 + gr) * SROW + k0 + gc);
#pragma unroll
            for (int mf = 0; mf < 2; mf++)
#pragma unroll
                for (int nf = 0; nf < 8; nf++)
                    mma_tf32(acc[mf][nf], afr[mf], bfr[nf]);
        }
        __syncthreads();
    }

#pragma unroll
    for (int mf = 0; mf < 2; mf++) {
        const int m = m0 + wm + mf * 16 + gr;
        const float bi0 = bias ? bias[m]     : 0.f;
        const float bi1 = bias ? bias[m + 8] : 0.f;
#pragma unroll
        for (int nf = 0; nf < 8; nf++) {
            const int n = n0 + wn + nf * 8 + gc * 2;
            float2 r0, r1;
            r0.x = acc[mf][nf][0] + bi0; r0.y = acc[mf][nf][1] + bi0;
            r1.x = acc[mf][nf][2] + bi1; r1.y = acc[mf][nf][3] + bi1;
            if (round_out) {
                r0.x = tf32r(r0.x); r0.y = tf32r(r0.y);
                r1.x = tf32r(r1.x); r1.y = tf32r(r1.y);
            }
            *(float2*)&C[(size_t)m * ldc + n]       = r0;
            *(float2*)&C[(size_t)(m + 8) * ldc + n] = r1;
        }
    }
}

// ---------------- single-pass fused attention, 2 CTAs/SM ----------------
// grid (64, 1, 4), 256 threads (8 warps: 2 wm x 4 qn). m-tile 64, n-tile 32.
// smem 102.4 KB -> 2 CTAs/SM; sibling CTA hides barrier/dependency bubbles.
#define OQ 0
#define OK 2304                        // Q: 64*36
#define OP (OK + 2 * 32 * 36)          // K: 2 x 32*36 -> 4608
#define OV (OP + 64 * 36)              // P: 64*36     -> 6912
#define OSUM (OV + 2 * 256 * 36)       // V: 2 x 256*36-> 25344
#define SMB_F (OSUM + 256)             // 25600 floats = 102400 B

__global__ void __launch_bounds__(256, 2) attn_pv(
    const float* __restrict__ q, const float* __restrict__ k,
    const float* __restrict__ v, float* __restrict__ o)
{
    extern __shared__ float smf[];
    float* sQ = smf + OQ;
    float* sK = smf + OK;
    float* sP = smf + OP;
    float* sV = smf + OV;
    float* sSum = smf + OSUM;

    const int b  = blockIdx.z;
    const int m0 = blockIdx.x * 64;
    const float* qb = q + (size_t)b * NNp * CQK + (size_t)m0 * CQK;
    const float* kb = k + (size_t)b * NNp * CQK;
    const float* vb = v + (size_t)b * CC * NNp;

    const int t = threadIdx.x;
    const int lane = t & 31, warp = t >> 5;
    const int wm = warp & 1;      // m sub-tile (2 x 32)
    const int qn = warp >> 1;     // QK: 8-wide n quadrant / PV: 64-wide c quadrant
    const int gr = lane >> 2, gc = lane & 3;

    const uint32_t sQb = smem_u32(sQ), sKb = smem_u32(sK), sVb = smem_u32(sV);

    // prologue: Q (64x32), K(0) (32x32), V(0) (256x32)
#pragma unroll
    for (int i = 0; i < 2; i++) {
        int idx = t + i * 256;
        int r = idx >> 3, c4 = (idx & 7) * 4;
        CP_ASYNC16(sQb + (uint32_t)(r * 36 + c4) * 4u, qb + (size_t)r * CQK + c4);
    }
    {
        int r = t >> 3, c4 = (t & 7) * 4;
        CP_ASYNC16(sKb + (uint32_t)(r * 36 + c4) * 4u, kb + (size_t)r * CQK + c4);
    }
#pragma unroll
    for (int i = 0; i < 8; i++) {
        int idx = t + i * 256;
        int r = idx >> 3, c4 = (idx & 7) * 4;
        CP_ASYNC16(sVb + (uint32_t)(r * 36 + c4) * 4u, vb + (size_t)r * NNp + c4);
    }
    CP_COMMIT(); CP_WAIT(0); __syncthreads();

    // hoist Q fragments (loop-invariant): 2 mf x 4 ks x 4 regs
    uint32_t afrQ[2][4][4];
#pragma unroll
    for (int mf = 0; mf < 2; mf++)
#pragma unroll
        for (int ks = 0; ks < 4; ks++)
            lda_frag(afrQ[mf][ks], sQ + (wm * 32 + mf * 16 + gr) * 36 + ks * 8 + gc, 36);

    float O[2][8][4];
#pragma unroll
    for (int mf = 0; mf < 2; mf++)
#pragma unroll
        for (int cf = 0; cf < 8; cf++)
#pragma unroll
            for (int j = 0; j < 4; j++) O[mf][cf][j] = 0.f;

    float rsum[2][2] = {{0.f, 0.f}, {0.f, 0.f}};

    for (int it = 0; it < 128; it++) {
        const int buf = it & 1;
        const float* sKbuf = sK + buf * (32 * 36);
        const float* sVbuf = sV + buf * (256 * 36);

        // ---- prefetch K(it+1), V(it+1) (overlaps whole body) ----
        if (it + 1 < 128) {
            {
                const float* src = kb + (size_t)(it + 1) * 32 * CQK;
                int r = t >> 3, c4 = (t & 7) * 4;
                CP_ASYNC16(sKb + (uint32_t)((buf ^ 1) * 32 * 36 + r * 36 + c4) * 4u,
                           src + (size_t)r * CQK + c4);
            }
            {
                const float* src = vb + (size_t)(it + 1) * 32;
                uint32_t dstb = sVb + (uint32_t)((buf ^ 1) * 256 * 36) * 4u;
#pragma unroll
                for (int i = 0; i < 8; i++) {
                    int idx = t + i * 256;
                    int r = idx >> 3, c4 = (idx & 7) * 4;
                    CP_ASYNC16(dstb + (uint32_t)(r * 36 + c4) * 4u,
                               src + (size_t)r * NNp + c4);
                }
            }
            CP_COMMIT();
        }

        // ---- S = Q x K(it)^T : warp 32m x 8n ----
        float sacc[2][4];
#pragma unroll
        for (int mf = 0; mf < 2; mf++)
#pragma unroll
            for (int j = 0; j < 4; j++) sacc[mf][j] = 0.f;
#pragma unroll
        for (int ks = 0; ks < 4; ks++) {
            uint32_t bfr[2];
            ldb_frag(bfr, sKbuf + (qn * 8 + gr) * 36 + ks * 8 + gc);
#pragma unroll
            for (int mf = 0; mf < 2; mf++)
                mma_tf32(sacc[mf], afrQ[mf][ks], bfr);
        }

        // ---- P = 2^S (unnormalized), accumulate row sums, stage to sP ----
#pragma unroll
        for (int mf = 0; mf < 2; mf++)
#pragma unroll
            for (int half = 0; half < 2; half++) {
                const int row = wm * 32 + mf * 16 + half * 8 + gr;
                const int col = qn * 8 + gc * 2;
                float p0 = ex2f(sacc[mf][half * 2]);
                float p1 = ex2f(sacc[mf][half * 2 + 1]);
                rsum[mf][half] += p0 + p1;
                *(float2*)&sP[row * 36 + col] = make_float2(p0, p1);
            }
        __syncthreads();   // publish P

        // ---- O += P x V(it)^T : warp 32m x 64c ----
#pragma unroll
        for (int ks = 0; ks < 4; ks++) {
            uint32_t afr[2][4], bfr[8][2];
#pragma unroll
            for (int mf = 0; mf < 2; mf++)
                lda_frag(afr[mf], sP + (wm * 32 + mf * 16 + gr) * 36 + ks * 8 + gc, 36);
#pragma unroll
            for (int cf = 0; cf < 8; cf++)
                ldb_frag(bfr[cf], sVbuf + (qn * 64 + cf * 8 + gr) * 36 + ks * 8 + gc);
#pragma unroll
            for (int mf = 0; mf < 2; mf++)
#pragma unroll
                for (int cf = 0; cf < 8; cf++)
                    mma_tf32(O[mf][cf], afr[mf], bfr[cf]);
        }

        if (it + 1 < 128) { CP_WAIT(0); }
        __syncthreads();   // publish K/V(it+1); orders PV reads before next P write
    }

    // ---- row-sum reduction across quadrants ----
#pragma unroll
    for (int mf = 0; mf < 2; mf++)
#pragma unroll
        for (int half = 0; half < 2; half++) {
            float r = rsum[mf][half];
            r += __shfl_xor_sync(0xffffffffu, r, 1);
            r += __shfl_xor_sync(0xffffffffu, r, 2);
            if (gc == 0)
                sSum[(wm * 32 + mf * 16 + half * 8 + gr) * 4 + qn] = r;
        }
    __syncthreads();

    // ---- epilogue: normalize + write O (tf32-rounded) ----
    float* ob = o + (size_t)b * NNp * CC + (size_t)m0 * CC;
#pragma unroll
    for (int mf = 0; mf < 2; mf++) {
        const int r0 = wm * 32 + mf * 16 + gr;
        const int r1 = r0 + 8;
        const float inv0 = 1.f / (sSum[r0 * 4] + sSum[r0 * 4 + 1] +
                                  sSum[r0 * 4 + 2] + sSum[r0 * 4 + 3]);
        const float inv1 = 1.f / (sSum[r1 * 4] + sSum[r1 * 4 + 1] +
                                  sSum[r1 * 4 + 2] + sSum[r1 * 4 + 3]);
#pragma unroll
        for (int cf = 0; cf < 8; cf++) {
            const int c = qn * 64 + cf * 8 + gc * 2;
            *(float2*)&ob[(size_t)r0 * CC + c] =
                make_float2(tf32r(O[mf][cf][0] * inv0), tf32r(O[mf][cf][1] * inv0));
            *(float2*)&ob[(size_t)r1 * CC + c] =
                make_float2(tf32r(O[mf][cf][2] * inv1), tf32r(O[mf][cf][3] * inv1));
        }
    }
}

// ---------------- fused prep: qk_proj FIRST, then transpose, then weights ----
__global__ void __launch_bounds__(256) fused_prep(
    const float* __restrict__ x,
    const float* __restrict__ Wq, const float* __restrict__ bq,
    const float* __restrict__ Wk, const float* __restrict__ bk,
    const float* __restrict__ Wv, const float* __restrict__ Wo,
    float* __restrict__ q, float* __restrict__ ko,
    float* __restrict__ xT, float* __restrict__ wv_r, float* __restrict__ wo_r)
{
    __shared__ float sbuf[6144];
    const int bid = blockIdx.x;
    const int t = threadIdx.x;

    if (bid < 128) {
        // qk projection
        const int m0 = (bid & 31) * 128;
        const int b  = bid >> 5;
        const float* xb = x + (size_t)b * CC * NNp;
        float (*sx)[128] = (float(*)[128])sbuf;         // 32x128
        float (*sw)[32]  = (float(*)[32])(sbuf + 4096); // 64x32

        const int mi   = t & 127;
        const int half = t >> 7;

        float acc[32];
        const float* bias = half ? bk : bq;
#pragma unroll
        for (int j = 0; j < 32; j++) acc[j] = bias[j];

        for (int c0 = 0; c0 < CC; c0 += 32) {
#pragma unroll
            for (int i = 0; i < 16; i++) {
                int idx = t + i * 256;
                int r = idx >> 7, mm = idx & 127;
                sx[r][mm] = xb[(size_t)(c0 + r) * NNp + m0 + mm];
            }
#pragma unroll
            for (int i = 0; i < 8; i++) {
                int idx = t + i * 256;
                int co = idx >> 5, cc = idx & 31;
                sw[co][cc] = (co < 32) ? Wq[co * 256 + c0 + cc]
                                       : Wk[(co - 32) * 256 + c0 + cc];
            }
            __syncthreads();
#pragma unroll
            for (int cc = 0; cc < 32; cc++) {
                float xv = sx[cc][mi];
#pragma unroll
                for (int j = 0; j < 32; j++) acc[j] += sw[half * 32 + j][cc] * xv;
            }
            __syncthreads();
        }

        const float scl = half ? 1.f : 1.4426950408889634f;  // log2(e) into q
        float* dst = (half ? ko : q) + (size_t)b * NNp * CQK + (size_t)(m0 + mi) * CQK;
#pragma unroll
        for (int j = 0; j < 32; j += 4)
            *(float4*)&dst[j] = make_float4(tf32r(acc[j] * scl), tf32r(acc[j + 1] * scl),
                                            tf32r(acc[j + 2] * scl), tf32r(acc[j + 3] * scl));
    } else if (bid < 4224) {
        // transpose: xT[b][n][c] = tf32(x[b][c][n])
        const int lb = bid - 128;
        const int bx = lb & 127;             // n-tile
        const int by = (lb >> 7) & 7;        // c-tile
        const int b  = lb >> 10;
        const float* src = x  + (size_t)b * CC * NNp;
        float*       dst = xT + (size_t)b * NNp * CC;
        const int c0 = bx * 32;              // over NNp
        const int r0 = by * 32;              // over CC
        const int tx = t & 31, ty = t >> 5;
        float (*tile)[33] = (float(*)[33])sbuf;
#pragma unroll
        for (int i = 0; i < 32; i += 8)
            tile[ty + i][tx] = tf32r(src[(size_t)(r0 + ty + i) * NNp + c0 + tx]);
        __syncthreads();
#pragma unroll
        for (int i = 0; i < 32; i += 8)
            dst[(size_t)(c0 + ty + i) * CC + r0 + tx] = tile[tx][ty + i];
    } else {
        // weight rounding
        const int i = (bid - 4224) * 256 + t;
        if (i < CC * CC)     wv_r[i] = tf32r(Wv[i]);
        if (i < CC * 2 * CC) wo_r[i] = tf32r(Wo[i]);
    }
}

// ---------------- launch ----------------
extern "C" void kernel_launch(void* const* d_in, const int* in_sizes, int n_in,
                              void* d_out, int out_size)
{
    const float* x  = (const float*)d_in[0];
    const float* Wq = (const float*)d_in[1];
    const float* bq = (const float*)d_in[2];
    const float* Wk = (const float*)d_in[3];
    const float* bk = (const float*)d_in[4];
    const float* Wv = (const float*)d_in[5];
    const float* bv = (const float*)d_in[6];
    const float* Wo = (const float*)d_in[7];
    const float* bo = (const float*)d_in[8];
    float* y = (float*)d_out;

    float *p_q, *p_k, *p_v, *p_o, *p_xT, *p_wv, *p_wo;
    cudaGetSymbolAddress((void**)&p_q,  g_q);
    cudaGetSymbolAddress((void**)&p_k,  g_k);
    cudaGetSymbolAddress((void**)&p_v,  g_v);
    cudaGetSymbolAddress((void**)&p_o,  g_o);
    cudaGetSymbolAddress((void**)&p_xT, g_xT);
    cudaGetSymbolAddress((void**)&p_wv, g_wv);
    cudaGetSymbolAddress((void**)&p_wo, g_wo);

    const size_t sX = (size_t)CC * NNp;

    const int SMEM_G = 4 * TILE_F * 4;
    cudaFuncSetAttribute(tc_gemm, cudaFuncAttributeMaxDynamicSharedMemorySize, SMEM_G);
    const int SMEM_B = SMB_F * 4;   // 102400 B -> 2 CTAs/SM
    cudaFuncSetAttribute(attn_pv, cudaFuncAttributeMaxDynamicSharedMemorySize, SMEM_B);

    // prep: qk projection + transpose + weight rounding, one launch
    fused_prep<<<4736, 256>>>(x, Wq, bq, Wk, bk, Wv, Wo,
                              p_q, p_k, p_xT, p_wv, p_wo);

    // v[c][n] = Wv @ x + bv
    tc_gemm<<<dim3(NNp / 128, CC / 128, BB), 256, SMEM_G>>>(
        p_wv, CC, 0,
        p_xT, CC, sX,
        nullptr, 0, 0, CC,
        p_v, NNp, sX,
        bv, CC, 1);

    // single-pass fused attention -> g_o [m][c]  (2 CTAs/SM, full-chip)
    attn_pv<<<dim3(NNp / 64, 1, BB), 256, SMEM_B>>>(p_q, p_k, p_v, p_o);

    // y = Wo @ concat(o, x)^T + bo
    tc_gemm<<<dim3(NNp / 128, CC / 128, BB), 256, SMEM_G>>>(
        p_wo, 2 * CC, 0,
        p_o, CC, sX,
        p_xT, CC, sX, CC,
        y, NNp, sX,
        bo, 2 * CC, 0);
}

// round 13
// speedup vs baseline: 1.1082x; 1.1082x over previous
#include <cuda_runtime.h>
#include <cstdint>
#include <math.h>

// Problem constants
#define BB   4
#define CC   256
#define CQK  32
#define NNp  4096

// ---------------- scratch ----------------
__device__ float  g_q [(size_t)BB * NNp * CQK];   // [b][m][32]  K-major, tf32, *log2e
__device__ float  g_k [(size_t)BB * NNp * CQK];   // [b][n][32]  K-major, tf32
__device__ float  g_v [(size_t)BB * CC * NNp];    // [b][c][n]   tf32
__device__ float  g_o [(size_t)BB * NNp * CC];    // [b][m][c]   tf32
__device__ float  g_wv[(size_t)CC * CC];
__device__ float  g_wo[(size_t)CC * 2 * CC];

// ---------------- helpers ----------------
__device__ __forceinline__ float tf32r(float x) {
    uint32_t y;
    asm("cvt.rna.tf32.f32 %0, %1;" : "=r"(y) : "f"(x));
    return __uint_as_float(y);
}
__device__ __forceinline__ uint32_t tf32r_u(float x) {
    uint32_t y;
    asm("cvt.rna.tf32.f32 %0, %1;" : "=r"(y) : "f"(x));
    return y;
}

__device__ __forceinline__ float ex2f(float x) {
    float y;
    asm("ex2.approx.f32 %0, %1;" : "=f"(y) : "f"(x));
    return y;
}

__device__ __forceinline__ uint32_t smem_u32(const void* p) {
    uint32_t a;
    asm("{ .reg .u64 t; cvta.to.shared.u64 t, %1; cvt.u32.u64 %0, t; }"
        : "=r"(a) : "l"(p));
    return a;
}

#define CP_ASYNC16(dst, src) \
    asm volatile("cp.async.cg.shared.global [%0], [%1], 16;" :: "r"(dst), "l"(src))
#define CP_COMMIT() asm volatile("cp.async.commit_group;" ::: "memory")
#define CP_WAIT(n)  asm volatile("cp.async.wait_group %0;" :: "n"(n) : "memory")

__device__ __forceinline__ void mma_tf32(float* d, const uint32_t* a, const uint32_t* b) {
    asm volatile(
        "mma.sync.aligned.m16n8k8.row.col.f32.tf32.tf32.f32 "
        "{%0,%1,%2,%3}, {%4,%5,%6,%7}, {%8,%9}, {%0,%1,%2,%3};"
        : "+f"(d[0]), "+f"(d[1]), "+f"(d[2]), "+f"(d[3])
        : "r"(a[0]), "r"(a[1]), "r"(a[2]), "r"(a[3]), "r"(b[0]), "r"(b[1]));
}

__device__ __forceinline__ void lda_frag(uint32_t* a, const float* p, int str) {
    a[0] = __float_as_uint(p[0]);
    a[1] = __float_as_uint(p[8 * str]);
    a[2] = __float_as_uint(p[4]);
    a[3] = __float_as_uint(p[8 * str + 4]);
}
__device__ __forceinline__ void ldb_frag(uint32_t* bf, const float* p) {
    bf[0] = __float_as_uint(p[0]);
    bf[1] = __float_as_uint(p[4]);
}

// ---------------- tf32 mma.sync GEMM with optional transposed-B sources ------
// D[M,N] = A[M,K] * B[N,K]^T (+bias[m]).
// Natural B source: rows n, k contiguous (ldb = row stride).
// Transposed B source (bT=1): memory is [k][n] (ldb = k-row stride, i.e. x[c][n]);
// tile loaded as 32k x 128n (stride 132), fragments read column-wise with
// in-fragment RNA tf32 rounding (source is raw fp32).
#define SROW 36
#define TILE_F (128 * SROW)
#define BTS 132

__global__ void __launch_bounds__(256, 2) tc_gemm(
    const float* __restrict__ A, int lda, size_t sAb,
    const float* __restrict__ B1, int ldb1, size_t sB1b, int bT1,
    const float* __restrict__ B2, int ldb2, size_t sB2b, int bT2, int ksplit,
    float* __restrict__ C, int ldc, size_t sCb,
    const float* __restrict__ bias, int K, int round_out)
{
    extern __shared__ float4 smem4[];
    float* sm = (float*)smem4;

    const int b = blockIdx.z;
    A  += (size_t)b * sAb;
    B1 += (size_t)b * sB1b;
    const float* B2p = B2 ? (B2 + (size_t)b * sB2b) : nullptr;
    C  += (size_t)b * sCb;

    const int n0 = blockIdx.x * 128;
    const int m0 = blockIdx.y * 128;
    const int t    = threadIdx.x;
    const int lane = t & 31;
    const int warp = t >> 5;
    const int wm = (warp & 3) * 32;
    const int wn = (warp >> 2) * 64;
    const int gr = lane >> 2;
    const int gc = lane & 3;

    const uint32_t sbase = smem_u32(sm);
    const int ldr = t >> 3;
    const int ldc4 = (t & 7) * 4;

    const int nk = K / 32;

    auto issue_tile = [&](int kb, int buf) {
        const int k0 = kb * 32;
        {
            const float* src = A + (size_t)(m0 + ldr) * lda + k0 + ldc4;
            uint32_t dst = sbase + (uint32_t)(buf * 2 * TILE_F) * 4u
                         + (uint32_t)(ldr * SROW + ldc4) * 4u;
#pragma unroll
            for (int i = 0; i < 4; i++)
                CP_ASYNC16(dst + (uint32_t)(i * 32 * SROW) * 4u,
                           src + (size_t)(i * 32) * lda);
        }
        {
            const float* Bp; int ldb, kk, bT;
            if (k0 < ksplit) { Bp = B1;  ldb = ldb1; kk = k0;          bT = bT1; }
            else             { Bp = B2p; ldb = ldb2; kk = k0 - ksplit; bT = bT2; }
            uint32_t bbase = sbase + (uint32_t)((buf * 2 + 1) * TILE_F) * 4u;
            if (bT) {
                // memory [k][n]: tile 32k x 128n, stride BTS
                const int r  = t >> 5;           // 0..7
                const int c4 = (t & 31) * 4;     // 0..124
                const float* src = Bp + (size_t)(kk + r) * ldb + n0 + c4;
#pragma unroll
                for (int i = 0; i < 4; i++)
                    CP_ASYNC16(bbase + (uint32_t)((r + i * 8) * BTS + c4) * 4u,
                               src + (size_t)(i * 8) * ldb);
            } else {
                const float* src = Bp + (size_t)(n0 + ldr) * ldb + kk + ldc4;
                uint32_t dst = bbase + (uint32_t)(ldr * SROW + ldc4) * 4u;
#pragma unroll
                for (int i = 0; i < 4; i++)
                    CP_ASYNC16(dst + (uint32_t)(i * 32 * SROW) * 4u,
                               src + (size_t)(i * 32) * ldb);
            }
        }
        CP_COMMIT();
    };

    float acc[2][8][4];
#pragma unroll
    for (int mf = 0; mf < 2; mf++)
#pragma unroll
        for (int nf = 0; nf < 8; nf++)
#pragma unroll
            for (int j = 0; j < 4; j++) acc[mf][nf][j] = 0.f;

    issue_tile(0, 0);

    for (int kb = 0; kb < nk; kb++) {
        const int buf = kb & 1;
        if (kb + 1 < nk) { issue_tile(kb + 1, buf ^ 1); CP_WAIT(1); }
        else             { CP_WAIT(0); }
        __syncthreads();

        const float* sA = sm + buf * 2 * TILE_F;
        const float* sB = sA + TILE_F;
        const int modeT = (kb * 32 < ksplit) ? bT1 : bT2;

#pragma unroll
        for (int ks = 0; ks < 4; ks++) {
            const int k0 = ks * 8;
            uint32_t afr[2][4], bfr[8][2];
#pragma unroll
            for (int mf = 0; mf < 2; mf++)
                lda_frag(afr[mf], sA + (wm + mf * 16 + gr) * SROW + k0 + gc, SROW);
            if (modeT) {
#pragma unroll
                for (int nf = 0; nf < 8; nf++) {
                    const int nn = wn + nf * 8 + gr;
                    bfr[nf][0] = tf32r_u(sB[(k0 + gc) * BTS + nn]);
                    bfr[nf][1] = tf32r_u(sB[(k0 + gc + 4) * BTS + nn]);
                }
            } else {
#pragma unroll
                for (int nf = 0; nf < 8; nf++)
                    ldb_frag(bfr[nf], sB + (wn + nf * 8 + gr) * SROW + k0 + gc);
            }
#pragma unroll
            for (int mf = 0; mf < 2; mf++)
#pragma unroll
                for (int nf = 0; nf < 8; nf++)
                    mma_tf32(acc[mf][nf], afr[mf], bfr[nf]);
        }
        __syncthreads();
    }

#pragma unroll
    for (int mf = 0; mf < 2; mf++) {
        const int m = m0 + wm + mf * 16 + gr;
        const float bi0 = bias ? bias[m]     : 0.f;
        const float bi1 = bias ? bias[m + 8] : 0.f;
#pragma unroll
        for (int nf = 0; nf < 8; nf++) {
            const int n = n0 + wn + nf * 8 + gc * 2;
            float2 r0, r1;
            r0.x = acc[mf][nf][0] + bi0; r0.y = acc[mf][nf][1] + bi0;
            r1.x = acc[mf][nf][2] + bi1; r1.y = acc[mf][nf][3] + bi1;
            if (round_out) {
                r0.x = tf32r(r0.x); r0.y = tf32r(r0.y);
                r1.x = tf32r(r1.x); r1.y = tf32r(r1.y);
            }
            *(float2*)&C[(size_t)m * ldc + n]       = r0;
            *(float2*)&C[(size_t)(m + 8) * ldc + n] = r1;
        }
    }
}

// ---------------- single-pass fused attention (R10 proven shape) -------------
// grid (32, 1, 4), 512 threads (16 warps: 4 wm x 4 qn). m-tile 128, n-tile 64.
#define OQ 0
#define OK 4608        // 2 x 64*36
#define OP 9216        // 128*68
#define OV 17920       // 2 x 256*68
#define OSUM 52736     // 128 x 4 floats
#define SMB_F 53248

__global__ void __launch_bounds__(512) attn_pv(
    const float* __restrict__ q, const float* __restrict__ k,
    const float* __restrict__ v, float* __restrict__ o)
{
    extern __shared__ float smf[];
    float* sQ = smf + OQ;
    float* sK = smf + OK;
    float* sP = smf + OP;
    float* sV = smf + OV;
    float* sSum = smf + OSUM;

    const int b  = blockIdx.z;
    const int m0 = blockIdx.x * 128;
    const float* qb = q + (size_t)b * NNp * CQK + (size_t)m0 * CQK;
    const float* kb = k + (size_t)b * NNp * CQK;
    const float* vb = v + (size_t)b * CC * NNp;

    const int t = threadIdx.x;
    const int lane = t & 31, warp = t >> 5;
    const int wm = warp & 3;
    const int qn = warp >> 2;
    const int gr = lane >> 2, gc = lane & 3;

    const uint32_t sQb = smem_u32(sQ), sKb = smem_u32(sK), sVb = smem_u32(sV);

    // prologue: Q, K(0), V(0)
#pragma unroll
    for (int i = 0; i < 2; i++) {
        int idx = t + i * 512;
        int r = idx >> 3, c4 = (idx & 7) * 4;
        CP_ASYNC16(sQb + (uint32_t)(r * 36 + c4) * 4u, qb + (size_t)r * CQK + c4);
    }
    {
        int r = t >> 3, c4 = (t & 7) * 4;
        CP_ASYNC16(sKb + (uint32_t)(r * 36 + c4) * 4u, kb + (size_t)r * CQK + c4);
    }
#pragma unroll
    for (int i = 0; i < 8; i++) {
        int idx = t + i * 512;
        int r = idx >> 4, c4 = (idx & 15) * 4;
        CP_ASYNC16(sVb + (uint32_t)(r * 68 + c4) * 4u, vb + (size_t)r * NNp + c4);
    }
    CP_COMMIT(); CP_WAIT(0); __syncthreads();

    // hoist Q fragments (loop-invariant)
    uint32_t afrQ[2][4][4];
#pragma unroll
    for (int mf = 0; mf < 2; mf++)
#pragma unroll
        for (int ks = 0; ks < 4; ks++)
            lda_frag(afrQ[mf][ks], sQ + (wm * 32 + mf * 16 + gr) * 36 + ks * 8 + gc, 36);

    float O[2][8][4];
#pragma unroll
    for (int mf = 0; mf < 2; mf++)
#pragma unroll
        for (int cf = 0; cf < 8; cf++)
#pragma unroll
            for (int j = 0; j < 4; j++) O[mf][cf][j] = 0.f;

    float rsum[2][2] = {{0.f, 0.f}, {0.f, 0.f}};

    for (int it = 0; it < 64; it++) {
        const int buf = it & 1;
        const float* sKbuf = sK + buf * (64 * 36);
        const float* sVbuf = sV + buf * (256 * 68);

        // prefetch K(it+1), V(it+1)
        if (it + 1 < 64) {
            {
                const float* src = kb + (size_t)(it + 1) * 64 * CQK;
                int r = t >> 3, c4 = (t & 7) * 4;
                CP_ASYNC16(sKb + (uint32_t)((buf ^ 1) * 64 * 36 + r * 36 + c4) * 4u,
                           src + (size_t)r * CQK + c4);
            }
            {
                const float* src = vb + (size_t)(it + 1) * 64;
                uint32_t dstb = sVb + (uint32_t)((buf ^ 1) * 256 * 68) * 4u;
#pragma unroll
                for (int i = 0; i < 8; i++) {
                    int idx = t + i * 512;
                    int r = idx >> 4, c4 = (idx & 15) * 4;
                    CP_ASYNC16(dstb + (uint32_t)(r * 68 + c4) * 4u,
                               src + (size_t)r * NNp + c4);
                }
            }
            CP_COMMIT();
        }

        // S = Q x K(it)^T : warp 32m x 16n
        float sacc[2][2][4];
#pragma unroll
        for (int mf = 0; mf < 2; mf++)
#pragma unroll
            for (int nf = 0; nf < 2; nf++)
#pragma unroll
                for (int j = 0; j < 4; j++) sacc[mf][nf][j] = 0.f;
#pragma unroll
        for (int ks = 0; ks < 4; ks++) {
            uint32_t bfr[2][2];
#pragma unroll
            for (int nf = 0; nf < 2; nf++)
                ldb_frag(bfr[nf], sKbuf + (qn * 16 + nf * 8 + gr) * 36 + ks * 8 + gc);
#pragma unroll
            for (int mf = 0; mf < 2; mf++)
#pragma unroll
                for (int nf = 0; nf < 2; nf++)
                    mma_tf32(sacc[mf][nf], afrQ[mf][ks], bfr[nf]);
        }

        // P = 2^S (unnormalized), accumulate row sums, stage to sP
#pragma unroll
        for (int mf = 0; mf < 2; mf++)
#pragma unroll
            for (int half = 0; half < 2; half++) {
                const int row = wm * 32 + mf * 16 + half * 8 + gr;
                float part = 0.f;
#pragma unroll
                for (int nf = 0; nf < 2; nf++) {
                    const int col = qn * 16 + nf * 8 + gc * 2;
                    float p0 = ex2f(sacc[mf][nf][half * 2]);
                    float p1 = ex2f(sacc[mf][nf][half * 2 + 1]);
                    part += p0 + p1;
                    *(float2*)&sP[row * 68 + col] = make_float2(p0, p1);
                }
                rsum[mf][half] += part;
            }
        __syncthreads();   // publish P

        // O += P x V(it)^T : warp 32m x 64c
#pragma unroll
        for (int ks = 0; ks < 8; ks++) {
            uint32_t afr[2][4], bfr[8][2];
#pragma unroll
            for (int mf = 0; mf < 2; mf++)
                lda_frag(afr[mf], sP + (wm * 32 + mf * 16 + gr) * 68 + ks * 8 + gc, 68);
#pragma unroll
            for (int cf = 0; cf < 8; cf++)
                ldb_frag(bfr[cf], sVbuf + (qn * 64 + cf * 8 + gr) * 68 + ks * 8 + gc);
#pragma unroll
            for (int mf = 0; mf < 2; mf++)
#pragma unroll
                for (int cf = 0; cf < 8; cf++)
                    mma_tf32(O[mf][cf], afr[mf], bfr[cf]);
        }

        if (it + 1 < 64) { CP_WAIT(0); }
        __syncthreads();
    }

    // row-sum reduction across quadrants
#pragma unroll
    for (int mf = 0; mf < 2; mf++)
#pragma unroll
        for (int half = 0; half < 2; half++) {
            float r = rsum[mf][half];
            r += __shfl_xor_sync(0xffffffffu, r, 1);
            r += __shfl_xor_sync(0xffffffffu, r, 2);
            if (gc == 0)
                sSum[(wm * 32 + mf * 16 + half * 8 + gr) * 4 + qn] = r;
        }
    __syncthreads();

    // epilogue: normalize + write O (tf32-rounded)
    float* ob = o + (size_t)b * NNp * CC + (size_t)m0 * CC;
#pragma unroll
    for (int mf = 0; mf < 2; mf++) {
        const int r0 = wm * 32 + mf * 16 + gr;
        const int r1 = r0 + 8;
        const float inv0 = 1.f / (sSum[r0 * 4] + sSum[r0 * 4 + 1] +
                                  sSum[r0 * 4 + 2] + sSum[r0 * 4 + 3]);
        const float inv1 = 1.f / (sSum[r1 * 4] + sSum[r1 * 4 + 1] +
                                  sSum[r1 * 4 + 2] + sSum[r1 * 4 + 3]);
#pragma unroll
        for (int cf = 0; cf < 8; cf++) {
            const int c = qn * 64 + cf * 8 + gc * 2;
            *(float2*)&ob[(size_t)r0 * CC + c] =
                make_float2(tf32r(O[mf][cf][0] * inv0), tf32r(O[mf][cf][1] * inv0));
            *(float2*)&ob[(size_t)r1 * CC + c] =
                make_float2(tf32r(O[mf][cf][2] * inv1), tf32r(O[mf][cf][3] * inv1));
        }
    }
}

// ---------------- fused prep: qk_proj + weight rounding (no transpose) -------
// blocks [0,128): qk projection. blocks [128,640): weight rounding.
__global__ void __launch_bounds__(256) fused_prep(
    const float* __restrict__ x,
    const float* __restrict__ Wq, const float* __restrict__ bq,
    const float* __restrict__ Wk, const float* __restrict__ bk,
    const float* __restrict__ Wv, const float* __restrict__ Wo,
    float* __restrict__ q, float* __restrict__ ko,
    float* __restrict__ wv_r, float* __restrict__ wo_r)
{
    __shared__ float sbuf[6144];
    const int bid = blockIdx.x;
    const int t = threadIdx.x;

    if (bid < 128) {
        // qk projection
        const int m0 = (bid & 31) * 128;
        const int b  = bid >> 5;
        const float* xb = x + (size_t)b * CC * NNp;
        float (*sx)[128] = (float(*)[128])sbuf;         // 32x128
        float (*sw)[32]  = (float(*)[32])(sbuf + 4096); // 64x32

        const int mi   = t & 127;
        const int half = t >> 7;

        float acc[32];
        const float* bias = half ? bk : bq;
#pragma unroll
        for (int j = 0; j < 32; j++) acc[j] = bias[j];

        for (int c0 = 0; c0 < CC; c0 += 32) {
#pragma unroll
            for (int i = 0; i < 16; i++) {
                int idx = t + i * 256;
                int r = idx >> 7, mm = idx & 127;
                sx[r][mm] = xb[(size_t)(c0 + r) * NNp + m0 + mm];
            }
#pragma unroll
            for (int i = 0; i < 8; i++) {
                int idx = t + i * 256;
                int co = idx >> 5, cc = idx & 31;
                sw[co][cc] = (co < 32) ? Wq[co * 256 + c0 + cc]
                                       : Wk[(co - 32) * 256 + c0 + cc];
            }
            __syncthreads();
#pragma unroll
            for (int cc = 0; cc < 32; cc++) {
                float xv = sx[cc][mi];
#pragma unroll
                for (int j = 0; j < 32; j++) acc[j] += sw[half * 32 + j][cc] * xv;
            }
            __syncthreads();
        }

        const float scl = half ? 1.f : 1.4426950408889634f;  // log2(e) into q
        float* dst = (half ? ko : q) + (size_t)b * NNp * CQK + (size_t)(m0 + mi) * CQK;
#pragma unroll
        for (int j = 0; j < 32; j += 4)
            *(float4*)&dst[j] = make_float4(tf32r(acc[j] * scl), tf32r(acc[j + 1] * scl),
                                            tf32r(acc[j + 2] * scl), tf32r(acc[j + 3] * scl));
    } else {
        // weight rounding
        const int i = (bid - 128) * 256 + t;
        if (i < CC * CC)     wv_r[i] = tf32r(Wv[i]);
        if (i < CC * 2 * CC) wo_r[i] = tf32r(Wo[i]);
    }
}

// ---------------- launch ----------------
extern "C" void kernel_launch(void* const* d_in, const int* in_sizes, int n_in,
                              void* d_out, int out_size)
{
    const float* x  = (const float*)d_in[0];
    const float* Wq = (const float*)d_in[1];
    const float* bq = (const float*)d_in[2];
    const float* Wk = (const float*)d_in[3];
    const float* bk = (const float*)d_in[4];
    const float* Wv = (const float*)d_in[5];
    const float* bv = (const float*)d_in[6];
    const float* Wo = (const float*)d_in[7];
    const float* bo = (const float*)d_in[8];
    float* y = (float*)d_out;

    float *p_q, *p_k, *p_v, *p_o, *p_wv, *p_wo;
    cudaGetSymbolAddress((void**)&p_q,  g_q);
    cudaGetSymbolAddress((void**)&p_k,  g_k);
    cudaGetSymbolAddress((void**)&p_v,  g_v);
    cudaGetSymbolAddress((void**)&p_o,  g_o);
    cudaGetSymbolAddress((void**)&p_wv, g_wv);
    cudaGetSymbolAddress((void**)&p_wo, g_wo);

    const size_t sX = (size_t)CC * NNp;

    const int SMEM_G = 4 * TILE_F * 4;
    cudaFuncSetAttribute(tc_gemm, cudaFuncAttributeMaxDynamicSharedMemorySize, SMEM_G);
    const int SMEM_B = SMB_F * 4;
    cudaFuncSetAttribute(attn_pv, cudaFuncAttributeMaxDynamicSharedMemorySize, SMEM_B);

    // prep: qk projection + weight rounding (640 blocks; no transpose anymore)
    fused_prep<<<640, 256>>>(x, Wq, bq, Wk, bk, Wv, Wo, p_q, p_k, p_wv, p_wo);

    // v[c][n] = Wv @ x + bv  (B = x read transposed-in-smem, RNA-rounded in-frag)
    tc_gemm<<<dim3(NNp / 128, CC / 128, BB), 256, SMEM_G>>>(
        p_wv, CC, 0,
        x, NNp, sX, 1,
        nullptr, 0, 0, 0, CC,
        p_v, NNp, sX,
        bv, CC, 1);

    // single-pass fused attention -> g_o [m][c]
    attn_pv<<<dim3(NNp / 128, 1, BB), 512, SMEM_B>>>(p_q, p_k, p_v, p_o);

    // y = Wo @ concat(o, x)^T + bo : B1 = o (natural), B2 = x (transposed mode)
    tc_gemm<<<dim3(NNp / 128, CC / 128, BB), 256, SMEM_G>>>(
        p_wo, 2 * CC, 0,
        p_o, CC, sX, 0,
        x, NNp, sX, 1, CC,
        y, NNp, sX,
        bo, 2 * CC, 0);
}

// round 14
// speedup vs baseline: 1.1320x; 1.0215x over previous
#include <cuda_runtime.h>
#include <cstdint>
#include <math.h>

// Problem constants
#define BB   4
#define CC   256
#define CQK  32
#define NNp  4096

// ---------------- scratch ----------------
__device__ float  g_q [(size_t)BB * NNp * CQK];   // [b][m][32]  K-major, tf32, *log2e
__device__ float  g_k [(size_t)BB * NNp * CQK];   // [b][n][32]  K-major, tf32
__device__ float  g_v [(size_t)BB * CC * NNp];    // [b][c][n]   tf32
__device__ float  g_o [(size_t)BB * NNp * CC];    // [b][m][c]   tf32
__device__ float  g_wv[(size_t)CC * CC];
__device__ float  g_wo[(size_t)CC * 2 * CC];

// ---------------- helpers ----------------
__device__ __forceinline__ float tf32r(float x) {
    uint32_t y;
    asm("cvt.rna.tf32.f32 %0, %1;" : "=r"(y) : "f"(x));
    return __uint_as_float(y);
}
__device__ __forceinline__ uint32_t tf32r_u(float x) {
    uint32_t y;
    asm("cvt.rna.tf32.f32 %0, %1;" : "=r"(y) : "f"(x));
    return y;
}

__device__ __forceinline__ float ex2f(float x) {
    float y;
    asm("ex2.approx.f32 %0, %1;" : "=f"(y) : "f"(x));
    return y;
}

__device__ __forceinline__ uint32_t smem_u32(const void* p) {
    uint32_t a;
    asm("{ .reg .u64 t; cvta.to.shared.u64 t, %1; cvt.u32.u64 %0, t; }"
        : "=r"(a) : "l"(p));
    return a;
}

#define CP_ASYNC16(dst, src) \
    asm volatile("cp.async.cg.shared.global [%0], [%1], 16;" :: "r"(dst), "l"(src))
#define CP_COMMIT() asm volatile("cp.async.commit_group;" ::: "memory")
#define CP_WAIT(n)  asm volatile("cp.async.wait_group %0;" :: "n"(n) : "memory")

__device__ __forceinline__ void mma_tf32(float* d, const uint32_t* a, const uint32_t* b) {
    asm volatile(
        "mma.sync.aligned.m16n8k8.row.col.f32.tf32.tf32.f32 "
        "{%0,%1,%2,%3}, {%4,%5,%6,%7}, {%8,%9}, {%0,%1,%2,%3};"
        : "+f"(d[0]), "+f"(d[1]), "+f"(d[2]), "+f"(d[3])
        : "r"(a[0]), "r"(a[1]), "r"(a[2]), "r"(a[3]), "r"(b[0]), "r"(b[1]));
}

__device__ __forceinline__ void ldsm_x4(uint32_t* r, uint32_t addr) {
    asm volatile("ldmatrix.sync.aligned.m8n8.x4.shared.b16 {%0,%1,%2,%3}, [%4];"
        : "=r"(r[0]), "=r"(r[1]), "=r"(r[2]), "=r"(r[3]) : "r"(addr));
}

__device__ __forceinline__ void lda_frag(uint32_t* a, const float* p, int str) {
    a[0] = __float_as_uint(p[0]);
    a[1] = __float_as_uint(p[8 * str]);
    a[2] = __float_as_uint(p[4]);
    a[3] = __float_as_uint(p[8 * str + 4]);
}
__device__ __forceinline__ void ldb_frag(uint32_t* bf, const float* p) {
    bf[0] = __float_as_uint(p[0]);
    bf[1] = __float_as_uint(p[4]);
}

// ---------------- tf32 mma.sync GEMM with optional transposed-B sources ------
#define SROW 36
#define TILE_F (128 * SROW)
#define BTS 132

__global__ void __launch_bounds__(256, 2) tc_gemm(
    const float* __restrict__ A, int lda, size_t sAb,
    const float* __restrict__ B1, int ldb1, size_t sB1b, int bT1,
    const float* __restrict__ B2, int ldb2, size_t sB2b, int bT2, int ksplit,
    float* __restrict__ C, int ldc, size_t sCb,
    const float* __restrict__ bias, int K, int round_out)
{
    extern __shared__ float4 smem4[];
    float* sm = (float*)smem4;

    const int b = blockIdx.z;
    A  += (size_t)b * sAb;
    B1 += (size_t)b * sB1b;
    const float* B2p = B2 ? (B2 + (size_t)b * sB2b) : nullptr;
    C  += (size_t)b * sCb;

    const int n0 = blockIdx.x * 128;
    const int m0 = blockIdx.y * 128;
    const int t    = threadIdx.x;
    const int lane = t & 31;
    const int warp = t >> 5;
    const int wm = (warp & 3) * 32;
    const int wn = (warp >> 2) * 64;
    const int gr = lane >> 2;
    const int gc = lane & 3;

    const uint32_t sbase = smem_u32(sm);
    const int ldr = t >> 3;
    const int ldc4 = (t & 7) * 4;

    const int nk = K / 32;

    auto issue_tile = [&](int kb, int buf) {
        const int k0 = kb * 32;
        {
            const float* src = A + (size_t)(m0 + ldr) * lda + k0 + ldc4;
            uint32_t dst = sbase + (uint32_t)(buf * 2 * TILE_F) * 4u
                         + (uint32_t)(ldr * SROW + ldc4) * 4u;
#pragma unroll
            for (int i = 0; i < 4; i++)
                CP_ASYNC16(dst + (uint32_t)(i * 32 * SROW) * 4u,
                           src + (size_t)(i * 32) * lda);
        }
        {
            const float* Bp; int ldb, kk, bT;
            if (k0 < ksplit) { Bp = B1;  ldb = ldb1; kk = k0;          bT = bT1; }
            else             { Bp = B2p; ldb = ldb2; kk = k0 - ksplit; bT = bT2; }
            uint32_t bbase = sbase + (uint32_t)((buf * 2 + 1) * TILE_F) * 4u;
            if (bT) {
                const int r  = t >> 5;
                const int c4 = (t & 31) * 4;
                const float* src = Bp + (size_t)(kk + r) * ldb + n0 + c4;
#pragma unroll
                for (int i = 0; i < 4; i++)
                    CP_ASYNC16(bbase + (uint32_t)((r + i * 8) * BTS + c4) * 4u,
                               src + (size_t)(i * 8) * ldb);
            } else {
                const float* src = Bp + (size_t)(n0 + ldr) * ldb + kk + ldc4;
                uint32_t dst = bbase + (uint32_t)(ldr * SROW + ldc4) * 4u;
#pragma unroll
                for (int i = 0; i < 4; i++)
                    CP_ASYNC16(dst + (uint32_t)(i * 32 * SROW) * 4u,
                               src + (size_t)(i * 32) * ldb);
            }
        }
        CP_COMMIT();
    };

    float acc[2][8][4];
#pragma unroll
    for (int mf = 0; mf < 2; mf++)
#pragma unroll
        for (int nf = 0; nf < 8; nf++)
#pragma unroll
            for (int j = 0; j < 4; j++) acc[mf][nf][j] = 0.f;

    issue_tile(0, 0);

    for (int kb = 0; kb < nk; kb++) {
        const int buf = kb & 1;
        if (kb + 1 < nk) { issue_tile(kb + 1, buf ^ 1); CP_WAIT(1); }
        else             { CP_WAIT(0); }
        __syncthreads();

        const float* sA = sm + buf * 2 * TILE_F;
        const float* sB = sA + TILE_F;
        const int modeT = (kb * 32 < ksplit) ? bT1 : bT2;

#pragma unroll
        for (int ks = 0; ks < 4; ks++) {
            const int k0 = ks * 8;
            uint32_t afr[2][4], bfr[8][2];
#pragma unroll
            for (int mf = 0; mf < 2; mf++)
                lda_frag(afr[mf], sA + (wm + mf * 16 + gr) * SROW + k0 + gc, SROW);
            if (modeT) {
#pragma unroll
                for (int nf = 0; nf < 8; nf++) {
                    const int nn = wn + nf * 8 + gr;
                    bfr[nf][0] = tf32r_u(sB[(k0 + gc) * BTS + nn]);
                    bfr[nf][1] = tf32r_u(sB[(k0 + gc + 4) * BTS + nn]);
                }
            } else {
#pragma unroll
                for (int nf = 0; nf < 8; nf++)
                    ldb_frag(bfr[nf], sB + (wn + nf * 8 + gr) * SROW + k0 + gc);
            }
#pragma unroll
            for (int mf = 0; mf < 2; mf++)
#pragma unroll
                for (int nf = 0; nf < 8; nf++)
                    mma_tf32(acc[mf][nf], afr[mf], bfr[nf]);
        }
        __syncthreads();
    }

#pragma unroll
    for (int mf = 0; mf < 2; mf++) {
        const int m = m0 + wm + mf * 16 + gr;
        const float bi0 = bias ? bias[m]     : 0.f;
        const float bi1 = bias ? bias[m + 8] : 0.f;
#pragma unroll
        for (int nf = 0; nf < 8; nf++) {
            const int n = n0 + wn + nf * 8 + gc * 2;
            float2 r0, r1;
            r0.x = acc[mf][nf][0] + bi0; r0.y = acc[mf][nf][1] + bi0;
            r1.x = acc[mf][nf][2] + bi1; r1.y = acc[mf][nf][3] + bi1;
            if (round_out) {
                r0.x = tf32r(r0.x); r0.y = tf32r(r0.y);
                r1.x = tf32r(r1.x); r1.y = tf32r(r1.y);
            }
            *(float2*)&C[(size_t)m * ldc + n]       = r0;
            *(float2*)&C[(size_t)(m + 8) * ldc + n] = r1;
        }
    }
}

// ---------------- single-pass fused attention (LDSM fragment loads) ----------
// grid (32, 1, 4), 512 threads (16 warps: 4 wm x 4 qn). m-tile 128, n-tile 64.
#define OQ 0
#define OK 4608        // 2 x 64*36
#define OP 9216        // 128*68
#define OV 17920       // 2 x 256*68
#define OSUM 52736     // 128 x 4 floats
#define SMB_F 53248

__global__ void __launch_bounds__(512) attn_pv(
    const float* __restrict__ q, const float* __restrict__ k,
    const float* __restrict__ v, float* __restrict__ o)
{
    extern __shared__ float smf[];
    float* sQ = smf + OQ;
    float* sK = smf + OK;
    float* sP = smf + OP;
    float* sV = smf + OV;
    float* sSum = smf + OSUM;

    const int b  = blockIdx.z;
    const int m0 = blockIdx.x * 128;
    const float* qb = q + (size_t)b * NNp * CQK + (size_t)m0 * CQK;
    const float* kb = k + (size_t)b * NNp * CQK;
    const float* vb = v + (size_t)b * CC * NNp;

    const int t = threadIdx.x;
    const int lane = t & 31, warp = t >> 5;
    const int wm = warp & 3;
    const int qn = warp >> 2;
    const int gr = lane >> 2, gc = lane & 3;

    const uint32_t sQb = smem_u32(sQ), sKb = smem_u32(sK);
    const uint32_t sPb = smem_u32(sP), sVb = smem_u32(sV);

    // LDSM per-lane row/col offsets
    // K (B, x4 covers 2 nf): rows qn*16 + (lane&7) + (lane&16)/2, col += (lane&8)/2
    const uint32_t kOff = (uint32_t)((qn * 16 + (lane & 7) + ((lane & 16) >> 1)) * 36
                                     + ((lane & 8) >> 1)) * 4u;
    // P (A, m16): rows wm*32 + mf*16 + (lane&15), col += (lane&16)/4
    const uint32_t pOff0 = (uint32_t)((wm * 32 + (lane & 15)) * 68
                                      + ((lane & 16) >> 2)) * 4u;
    // V (B, x4 covers 2 cf): rows qn*64 + cfp*16 + (lane&7) + (lane&16)/2, col += (lane&8)/2
    const uint32_t vOff = (uint32_t)((qn * 64 + (lane & 7) + ((lane & 16) >> 1)) * 68
                                     + ((lane & 8) >> 1)) * 4u;

    // prologue: Q, K(0), V(0)
#pragma unroll
    for (int i = 0; i < 2; i++) {
        int idx = t + i * 512;
        int r = idx >> 3, c4 = (idx & 7) * 4;
        CP_ASYNC16(sQb + (uint32_t)(r * 36 + c4) * 4u, qb + (size_t)r * CQK + c4);
    }
    {
        int r = t >> 3, c4 = (t & 7) * 4;
        CP_ASYNC16(sKb + (uint32_t)(r * 36 + c4) * 4u, kb + (size_t)r * CQK + c4);
    }
#pragma unroll
    for (int i = 0; i < 8; i++) {
        int idx = t + i * 512;
        int r = idx >> 4, c4 = (idx & 15) * 4;
        CP_ASYNC16(sVb + (uint32_t)(r * 68 + c4) * 4u, vb + (size_t)r * NNp + c4);
    }
    CP_COMMIT(); CP_WAIT(0); __syncthreads();

    // hoist Q fragments (loop-invariant)
    uint32_t afrQ[2][4][4];
#pragma unroll
    for (int mf = 0; mf < 2; mf++)
#pragma unroll
        for (int ks = 0; ks < 4; ks++)
            lda_frag(afrQ[mf][ks], sQ + (wm * 32 + mf * 16 + gr) * 36 + ks * 8 + gc, 36);

    float O[2][8][4];
#pragma unroll
    for (int mf = 0; mf < 2; mf++)
#pragma unroll
        for (int cf = 0; cf < 8; cf++)
#pragma unroll
            for (int j = 0; j < 4; j++) O[mf][cf][j] = 0.f;

    float rsum[2][2] = {{0.f, 0.f}, {0.f, 0.f}};

    for (int it = 0; it < 64; it++) {
        const int buf = it & 1;
        const uint32_t sKbase = sKb + (uint32_t)(buf * 64 * 36) * 4u + kOff;
        const uint32_t sVbase = sVb + (uint32_t)(buf * 256 * 68) * 4u + vOff;

        // prefetch K(it+1), V(it+1)
        if (it + 1 < 64) {
            {
                const float* src = kb + (size_t)(it + 1) * 64 * CQK;
                int r = t >> 3, c4 = (t & 7) * 4;
                CP_ASYNC16(sKb + (uint32_t)((buf ^ 1) * 64 * 36 + r * 36 + c4) * 4u,
                           src + (size_t)r * CQK + c4);
            }
            {
                const float* src = vb + (size_t)(it + 1) * 64;
                uint32_t dstb = sVb + (uint32_t)((buf ^ 1) * 256 * 68) * 4u;
#pragma unroll
                for (int i = 0; i < 8; i++) {
                    int idx = t + i * 512;
                    int r = idx >> 4, c4 = (idx & 15) * 4;
                    CP_ASYNC16(dstb + (uint32_t)(r * 68 + c4) * 4u,
                               src + (size_t)r * NNp + c4);
                }
            }
            CP_COMMIT();
        }

        // S = Q x K(it)^T : warp 32m x 16n  (K frags via 1 LDSM.x4 per ks)
        float sacc[2][2][4];
#pragma unroll
        for (int mf = 0; mf < 2; mf++)
#pragma unroll
            for (int nf = 0; nf < 2; nf++)
#pragma unroll
                for (int j = 0; j < 4; j++) sacc[mf][nf][j] = 0.f;
#pragma unroll
        for (int ks = 0; ks < 4; ks++) {
            uint32_t bfr[4];   // [nf0 b0, nf0 b1, nf1 b0, nf1 b1]
            ldsm_x4(bfr, sKbase + (uint32_t)(ks * 8) * 4u);
#pragma unroll
            for (int mf = 0; mf < 2; mf++) {
                mma_tf32(sacc[mf][0], afrQ[mf][ks], bfr);
                mma_tf32(sacc[mf][1], afrQ[mf][ks], bfr + 2);
            }
        }

        // P = 2^S (unnormalized), accumulate row sums, stage to sP
#pragma unroll
        for (int mf = 0; mf < 2; mf++)
#pragma unroll
            for (int half = 0; half < 2; half++) {
                const int row = wm * 32 + mf * 16 + half * 8 + gr;
                float part = 0.f;
#pragma unroll
                for (int nf = 0; nf < 2; nf++) {
                    const int col = qn * 16 + nf * 8 + gc * 2;
                    float p0 = ex2f(sacc[mf][nf][half * 2]);
                    float p1 = ex2f(sacc[mf][nf][half * 2 + 1]);
                    part += p0 + p1;
                    *(float2*)&sP[row * 68 + col] = make_float2(p0, p1);
                }
                rsum[mf][half] += part;
            }
        __syncthreads();   // publish P

        // O += P x V(it)^T : warp 32m x 64c (A: 2 LDSM.x4, B: 4 LDSM.x4 per ks)
#pragma unroll
        for (int ks = 0; ks < 8; ks++) {
            uint32_t afr[2][4], bfr[4][4];
            ldsm_x4(afr[0], sPb + pOff0 + (uint32_t)(ks * 8) * 4u);
            ldsm_x4(afr[1], sPb + pOff0 + (uint32_t)(16 * 68 + ks * 8) * 4u);
#pragma unroll
            for (int cfp = 0; cfp < 4; cfp++)
                ldsm_x4(bfr[cfp], sVbase + (uint32_t)(cfp * 16 * 68 + ks * 8) * 4u);
#pragma unroll
            for (int mf = 0; mf < 2; mf++)
#pragma unroll
                for (int cfp = 0; cfp < 4; cfp++) {
                    mma_tf32(O[mf][cfp * 2],     afr[mf], bfr[cfp]);
                    mma_tf32(O[mf][cfp * 2 + 1], afr[mf], bfr[cfp] + 2);
                }
        }

        if (it + 1 < 64) { CP_WAIT(0); }
        __syncthreads();
    }

    // row-sum reduction across quadrants
#pragma unroll
    for (int mf = 0; mf < 2; mf++)
#pragma unroll
        for (int half = 0; half < 2; half++) {
            float r = rsum[mf][half];
            r += __shfl_xor_sync(0xffffffffu, r, 1);
            r += __shfl_xor_sync(0xffffffffu, r, 2);
            if (gc == 0)
                sSum[(wm * 32 + mf * 16 + half * 8 + gr) * 4 + qn] = r;
        }
    __syncthreads();

    // epilogue: normalize + write O (tf32-rounded)
    float* ob = o + (size_t)b * NNp * CC + (size_t)m0 * CC;
#pragma unroll
    for (int mf = 0; mf < 2; mf++) {
        const int r0 = wm * 32 + mf * 16 + gr;
        const int r1 = r0 + 8;
        const float inv0 = 1.f / (sSum[r0 * 4] + sSum[r0 * 4 + 1] +
                                  sSum[r0 * 4 + 2] + sSum[r0 * 4 + 3]);
        const float inv1 = 1.f / (sSum[r1 * 4] + sSum[r1 * 4 + 1] +
                                  sSum[r1 * 4 + 2] + sSum[r1 * 4 + 3]);
#pragma unroll
        for (int cf = 0; cf < 8; cf++) {
            const int c = qn * 64 + cf * 8 + gc * 2;
            *(float2*)&ob[(size_t)r0 * CC + c] =
                make_float2(tf32r(O[mf][cf][0] * inv0), tf32r(O[mf][cf][1] * inv0));
            *(float2*)&ob[(size_t)r1 * CC + c] =
                make_float2(tf32r(O[mf][cf][2] * inv1), tf32r(O[mf][cf][3] * inv1));
        }
    }
}

// ---------------- fused prep: qk_proj + weight rounding ----------------------
__global__ void __launch_bounds__(256) fused_prep(
    const float* __restrict__ x,
    const float* __restrict__ Wq, const float* __restrict__ bq,
    const float* __restrict__ Wk, const float* __restrict__ bk,
    const float* __restrict__ Wv, const float* __restrict__ Wo,
    float* __restrict__ q, float* __restrict__ ko,
    float* __restrict__ wv_r, float* __restrict__ wo_r)
{
    __shared__ float sbuf[6144];
    const int bid = blockIdx.x;
    const int t = threadIdx.x;

    if (bid < 128) {
        const int m0 = (bid & 31) * 128;
        const int b  = bid >> 5;
        const float* xb = x + (size_t)b * CC * NNp;
        float (*sx)[128] = (float(*)[128])sbuf;
        float (*sw)[32]  = (float(*)[32])(sbuf + 4096);

        const int mi   = t & 127;
        const int half = t >> 7;

        float acc[32];
        const float* bias = half ? bk : bq;
#pragma unroll
        for (int j = 0; j < 32; j++) acc[j] = bias[j];

        for (int c0 = 0; c0 < CC; c0 += 32) {
#pragma unroll
            for (int i = 0; i < 16; i++) {
                int idx = t + i * 256;
                int r = idx >> 7, mm = idx & 127;
                sx[r][mm] = xb[(size_t)(c0 + r) * NNp + m0 + mm];
            }
#pragma unroll
            for (int i = 0; i < 8; i++) {
                int idx = t + i * 256;
                int co = idx >> 5, cc = idx & 31;
                sw[co][cc] = (co < 32) ? Wq[co * 256 + c0 + cc]
                                       : Wk[(co - 32) * 256 + c0 + cc];
            }
            __syncthreads();
#pragma unroll
            for (int cc = 0; cc < 32; cc++) {
                float xv = sx[cc][mi];
#pragma unroll
                for (int j = 0; j < 32; j++) acc[j] += sw[half * 32 + j][cc] * xv;
            }
            __syncthreads();
        }

        const float scl = half ? 1.f : 1.4426950408889634f;
        float* dst = (half ? ko : q) + (size_t)b * NNp * CQK + (size_t)(m0 + mi) * CQK;
#pragma unroll
        for (int j = 0; j < 32; j += 4)
            *(float4*)&dst[j] = make_float4(tf32r(acc[j] * scl), tf32r(acc[j + 1] * scl),
                                            tf32r(acc[j + 2] * scl), tf32r(acc[j + 3] * scl));
    } else {
        const int i = (bid - 128) * 256 + t;
        if (i < CC * CC)     wv_r[i] = tf32r(Wv[i]);
        if (i < CC * 2 * CC) wo_r[i] = tf32r(Wo[i]);
    }
}

// ---------------- launch ----------------
extern "C" void kernel_launch(void* const* d_in, const int* in_sizes, int n_in,
                              void* d_out, int out_size)
{
    const float* x  = (const float*)d_in[0];
    const float* Wq = (const float*)d_in[1];
    const float* bq = (const float*)d_in[2];
    const float* Wk = (const float*)d_in[3];
    const float* bk = (const float*)d_in[4];
    const float* Wv = (const float*)d_in[5];
    const float* bv = (const float*)d_in[6];
    const float* Wo = (const float*)d_in[7];
    const float* bo = (const float*)d_in[8];
    float* y = (float*)d_out;

    float *p_q, *p_k, *p_v, *p_o, *p_wv, *p_wo;
    cudaGetSymbolAddress((void**)&p_q,  g_q);
    cudaGetSymbolAddress((void**)&p_k,  g_k);
    cudaGetSymbolAddress((void**)&p_v,  g_v);
    cudaGetSymbolAddress((void**)&p_o,  g_o);
    cudaGetSymbolAddress((void**)&p_wv, g_wv);
    cudaGetSymbolAddress((void**)&p_wo, g_wo);

    const size_t sX = (size_t)CC * NNp;

    const int SMEM_G = 4 * TILE_F * 4;
    cudaFuncSetAttribute(tc_gemm, cudaFuncAttributeMaxDynamicSharedMemorySize, SMEM_G);
    const int SMEM_B = SMB_F * 4;
    cudaFuncSetAttribute(attn_pv, cudaFuncAttributeMaxDynamicSharedMemorySize, SMEM_B);

    // prep: qk projection + weight rounding
    fused_prep<<<640, 256>>>(x, Wq, bq, Wk, bk, Wv, Wo, p_q, p_k, p_wv, p_wo);

    // v[c][n] = Wv @ x + bv  (B = x, transposed mode)
    tc_gemm<<<dim3(NNp / 128, CC / 128, BB), 256, SMEM_G>>>(
        p_wv, CC, 0,
        x, NNp, sX, 1,
        nullptr, 0, 0, 0, CC,
        p_v, NNp, sX,
        bv, CC, 1);

    // single-pass fused attention -> g_o [m][c]
    attn_pv<<<dim3(NNp / 128, 1, BB), 512, SMEM_B>>>(p_q, p_k, p_v, p_o);

    // y = Wo @ concat(o, x)^T + bo
    tc_gemm<<<dim3(NNp / 128, CC / 128, BB), 256, SMEM_G>>>(
        p_wo, 2 * CC, 0,
        p_o, CC, sX, 0,
        x, NNp, sX, 1, CC,
        y, NNp, sX,
        bo, 2 * CC, 0);
}

// round 15
// speedup vs baseline: 1.1326x; 1.0005x over previous
#include <cuda_runtime.h>
#include <cstdint>
#include <math.h>

// Problem constants
#define BB   4
#define CC   256
#define CQK  32
#define NNp  4096

// ---------------- scratch ----------------
__device__ float  g_q [(size_t)BB * NNp * CQK];   // [b][m][32]  K-major, tf32, *log2e
__device__ float  g_k [(size_t)BB * NNp * CQK];   // [b][n][32]  K-major, tf32
__device__ float  g_v [(size_t)BB * CC * NNp];    // [b][c][n]   tf32
__device__ float  g_o [(size_t)BB * NNp * CC];    // [b][m][c]   tf32

// ---------------- helpers ----------------
__device__ __forceinline__ float tf32r(float x) {
    uint32_t y;
    asm("cvt.rna.tf32.f32 %0, %1;" : "=r"(y) : "f"(x));
    return __uint_as_float(y);
}
__device__ __forceinline__ uint32_t tf32r_u(float x) {
    uint32_t y;
    asm("cvt.rna.tf32.f32 %0, %1;" : "=r"(y) : "f"(x));
    return y;
}
__device__ __forceinline__ uint32_t tf32r_r(uint32_t x) {
    uint32_t y;
    asm("cvt.rna.tf32.f32 %0, %1;" : "=r"(y) : "f"(__uint_as_float(x)));
    return y;
}

__device__ __forceinline__ float ex2f(float x) {
    float y;
    asm("ex2.approx.f32 %0, %1;" : "=f"(y) : "f"(x));
    return y;
}

__device__ __forceinline__ uint32_t smem_u32(const void* p) {
    uint32_t a;
    asm("{ .reg .u64 t; cvta.to.shared.u64 t, %1; cvt.u32.u64 %0, t; }"
        : "=r"(a) : "l"(p));
    return a;
}

#define CP_ASYNC16(dst, src) \
    asm volatile("cp.async.cg.shared.global [%0], [%1], 16;" :: "r"(dst), "l"(src))
#define CP_COMMIT() asm volatile("cp.async.commit_group;" ::: "memory")
#define CP_WAIT(n)  asm volatile("cp.async.wait_group %0;" :: "n"(n) : "memory")

__device__ __forceinline__ void mma_tf32(float* d, const uint32_t* a, const uint32_t* b) {
    asm volatile(
        "mma.sync.aligned.m16n8k8.row.col.f32.tf32.tf32.f32 "
        "{%0,%1,%2,%3}, {%4,%5,%6,%7}, {%8,%9}, {%0,%1,%2,%3};"
        : "+f"(d[0]), "+f"(d[1]), "+f"(d[2]), "+f"(d[3])
        : "r"(a[0]), "r"(a[1]), "r"(a[2]), "r"(a[3]), "r"(b[0]), "r"(b[1]));
}

__device__ __forceinline__ void ldsm_x4(uint32_t* r, uint32_t addr) {
    asm volatile("ldmatrix.sync.aligned.m8n8.x4.shared.b16 {%0,%1,%2,%3}, [%4];"
        : "=r"(r[0]), "=r"(r[1]), "=r"(r[2]), "=r"(r[3]) : "r"(addr));
}

__device__ __forceinline__ void lda_frag(uint32_t* a, const float* p, int str) {
    a[0] = __float_as_uint(p[0]);
    a[1] = __float_as_uint(p[8 * str]);
    a[2] = __float_as_uint(p[4]);
    a[3] = __float_as_uint(p[8 * str + 4]);
}

// ---------------- tf32 mma.sync GEMM (LDSM fragments, in-frag weight round) --
// D[M,N] = A[M,K] * B[N,K]^T (+bias[m]).  A = raw fp32 weights (rounded in-frag).
// Natural B (bT=0): rows n, k contiguous, pre-rounded tf32.
// Transposed B (bT=1): memory is [k][n] raw fp32; rounded in-frag (scalar path).
#define SROW 36
#define TILE_F (128 * SROW)
#define BTS 132

__global__ void __launch_bounds__(256, 2) tc_gemm(
    const float* __restrict__ A, int lda, size_t sAb,
    const float* __restrict__ B1, int ldb1, size_t sB1b, int bT1,
    const float* __restrict__ B2, int ldb2, size_t sB2b, int bT2, int ksplit,
    float* __restrict__ C, int ldc, size_t sCb,
    const float* __restrict__ bias, int K, int round_out)
{
    extern __shared__ float4 smem4[];
    float* sm = (float*)smem4;

    const int b = blockIdx.z;
    A  += (size_t)b * sAb;
    B1 += (size_t)b * sB1b;
    const float* B2p = B2 ? (B2 + (size_t)b * sB2b) : nullptr;
    C  += (size_t)b * sCb;

    const int n0 = blockIdx.x * 128;
    const int m0 = blockIdx.y * 128;
    const int t    = threadIdx.x;
    const int lane = t & 31;
    const int warp = t >> 5;
    const int wm = (warp & 3) * 32;
    const int wn = (warp >> 2) * 64;
    const int gr = lane >> 2;
    const int gc = lane & 3;

    const uint32_t sbase = smem_u32(sm);
    const int ldr = t >> 3;
    const int ldc4 = (t & 7) * 4;

    // LDSM per-lane offsets (float units)
    // A (m16k8 x4): rows wm + mf*16 + (lane&15), col k0 + ((lane&16)>>2)
    const uint32_t aOff = (uint32_t)((wm + (lane & 15)) * SROW + ((lane & 16) >> 2));
    // B natural (two n8k8 pairs): rows wn + nfp*16 + (lane&7) + ((lane&16)>>1),
    // col k0 + ((lane&8)>>1)
    const uint32_t bOff = (uint32_t)((wn + (lane & 7) + ((lane & 16) >> 1)) * SROW
                                     + ((lane & 8) >> 1));

    const int nk = K / 32;

    auto issue_tile = [&](int kb, int buf) {
        const int k0 = kb * 32;
        {
            const float* src = A + (size_t)(m0 + ldr) * lda + k0 + ldc4;
            uint32_t dst = sbase + (uint32_t)(buf * 2 * TILE_F) * 4u
                         + (uint32_t)(ldr * SROW + ldc4) * 4u;
#pragma unroll
            for (int i = 0; i < 4; i++)
                CP_ASYNC16(dst + (uint32_t)(i * 32 * SROW) * 4u,
                           src + (size_t)(i * 32) * lda);
        }
        {
            const float* Bp; int ldb, kk, bT;
            if (k0 < ksplit) { Bp = B1;  ldb = ldb1; kk = k0;          bT = bT1; }
            else             { Bp = B2p; ldb = ldb2; kk = k0 - ksplit; bT = bT2; }
            uint32_t bbase = sbase + (uint32_t)((buf * 2 + 1) * TILE_F) * 4u;
            if (bT) {
                const int r  = t >> 5;
                const int c4 = (t & 31) * 4;
                const float* src = Bp + (size_t)(kk + r) * ldb + n0 + c4;
#pragma unroll
                for (int i = 0; i < 4; i++)
                    CP_ASYNC16(bbase + (uint32_t)((r + i * 8) * BTS + c4) * 4u,
                               src + (size_t)(i * 8) * ldb);
            } else {
                const float* src = Bp + (size_t)(n0 + ldr) * ldb + kk + ldc4;
                uint32_t dst = bbase + (uint32_t)(ldr * SROW + ldc4) * 4u;
#pragma unroll
                for (int i = 0; i < 4; i++)
                    CP_ASYNC16(dst + (uint32_t)(i * 32 * SROW) * 4u,
                               src + (size_t)(i * 32) * ldb);
            }
        }
        CP_COMMIT();
    };

    float acc[2][8][4];
#pragma unroll
    for (int mf = 0; mf < 2; mf++)
#pragma unroll
        for (int nf = 0; nf < 8; nf++)
#pragma unroll
            for (int j = 0; j < 4; j++) acc[mf][nf][j] = 0.f;

    issue_tile(0, 0);

    for (int kb = 0; kb < nk; kb++) {
        const int buf = kb & 1;
        if (kb + 1 < nk) { issue_tile(kb + 1, buf ^ 1); CP_WAIT(1); }
        else             { CP_WAIT(0); }
        __syncthreads();

        const uint32_t sAu = sbase + (uint32_t)(buf * 2 * TILE_F) * 4u;
        const uint32_t sBu = sAu + (uint32_t)TILE_F * 4u;
        const float* sB = sm + (buf * 2 + 1) * TILE_F;
        const int modeT = (kb * 32 < ksplit) ? bT1 : bT2;

#pragma unroll
        for (int ks = 0; ks < 4; ks++) {
            const int k0 = ks * 8;
            // A fragments: raw weights -> LDSM + in-frag tf32 round
            uint32_t afr[2][4];
#pragma unroll
            for (int mf = 0; mf < 2; mf++) {
                ldsm_x4(afr[mf], sAu + (aOff + (uint32_t)(mf * 16 * SROW + k0)) * 4u);
#pragma unroll
                for (int j = 0; j < 4; j++) afr[mf][j] = tf32r_r(afr[mf][j]);
            }
            if (modeT) {
                uint32_t bfr[8][2];
#pragma unroll
                for (int nf = 0; nf < 8; nf++) {
                    const int nn = wn + nf * 8 + gr;
                    bfr[nf][0] = tf32r_u(sB[(k0 + gc) * BTS + nn]);
                    bfr[nf][1] = tf32r_u(sB[(k0 + gc + 4) * BTS + nn]);
                }
#pragma unroll
                for (int mf = 0; mf < 2; mf++)
#pragma unroll
                    for (int nf = 0; nf < 8; nf++)
                        mma_tf32(acc[mf][nf], afr[mf], bfr[nf]);
            } else {
                uint32_t bfr[4][4];
#pragma unroll
                for (int nfp = 0; nfp < 4; nfp++)
                    ldsm_x4(bfr[nfp], sBu + (bOff + (uint32_t)(nfp * 16 * SROW + k0)) * 4u);
#pragma unroll
                for (int mf = 0; mf < 2; mf++)
#pragma unroll
                    for (int nfp = 0; nfp < 4; nfp++) {
                        mma_tf32(acc[mf][nfp * 2],     afr[mf], bfr[nfp]);
                        mma_tf32(acc[mf][nfp * 2 + 1], afr[mf], bfr[nfp] + 2);
                    }
            }
        }
        __syncthreads();
    }

#pragma unroll
    for (int mf = 0; mf < 2; mf++) {
        const int m = m0 + wm + mf * 16 + gr;
        const float bi0 = bias ? bias[m]     : 0.f;
        const float bi1 = bias ? bias[m + 8] : 0.f;
#pragma unroll
        for (int nf = 0; nf < 8; nf++) {
            const int n = n0 + wn + nf * 8 + gc * 2;
            float2 r0, r1;
            r0.x = acc[mf][nf][0] + bi0; r0.y = acc[mf][nf][1] + bi0;
            r1.x = acc[mf][nf][2] + bi1; r1.y = acc[mf][nf][3] + bi1;
            if (round_out) {
                r0.x = tf32r(r0.x); r0.y = tf32r(r0.y);
                r1.x = tf32r(r1.x); r1.y = tf32r(r1.y);
            }
            *(float2*)&C[(size_t)m * ldc + n]       = r0;
            *(float2*)&C[(size_t)(m + 8) * ldc + n] = r1;
        }
    }
}

// ---------------- single-pass fused attention (R14 proven, LDSM) -------------
// grid (32, 1, 4), 512 threads (16 warps: 4 wm x 4 qn). m-tile 128, n-tile 64.
#define OQ 0
#define OK 4608        // 2 x 64*36
#define OP 9216        // 128*68
#define OV 17920       // 2 x 256*68
#define OSUM 52736     // 128 x 4 floats
#define SMB_F 53248

__global__ void __launch_bounds__(512) attn_pv(
    const float* __restrict__ q, const float* __restrict__ k,
    const float* __restrict__ v, float* __restrict__ o)
{
    extern __shared__ float smf[];
    float* sQ = smf + OQ;
    float* sK = smf + OK;
    float* sP = smf + OP;
    float* sV = smf + OV;
    float* sSum = smf + OSUM;

    const int b  = blockIdx.z;
    const int m0 = blockIdx.x * 128;
    const float* qb = q + (size_t)b * NNp * CQK + (size_t)m0 * CQK;
    const float* kb = k + (size_t)b * NNp * CQK;
    const float* vb = v + (size_t)b * CC * NNp;

    const int t = threadIdx.x;
    const int lane = t & 31, warp = t >> 5;
    const int wm = warp & 3;
    const int qn = warp >> 2;
    const int gr = lane >> 2, gc = lane & 3;

    const uint32_t sQb = smem_u32(sQ), sKb = smem_u32(sK);
    const uint32_t sPb = smem_u32(sP), sVb = smem_u32(sV);

    const uint32_t kOff = (uint32_t)((qn * 16 + (lane & 7) + ((lane & 16) >> 1)) * 36
                                     + ((lane & 8) >> 1)) * 4u;
    const uint32_t pOff0 = (uint32_t)((wm * 32 + (lane & 15)) * 68
                                      + ((lane & 16) >> 2)) * 4u;
    const uint32_t vOff = (uint32_t)((qn * 64 + (lane & 7) + ((lane & 16) >> 1)) * 68
                                     + ((lane & 8) >> 1)) * 4u;

    // prologue: Q, K(0), V(0)
#pragma unroll
    for (int i = 0; i < 2; i++) {
        int idx = t + i * 512;
        int r = idx >> 3, c4 = (idx & 7) * 4;
        CP_ASYNC16(sQb + (uint32_t)(r * 36 + c4) * 4u, qb + (size_t)r * CQK + c4);
    }
    {
        int r = t >> 3, c4 = (t & 7) * 4;
        CP_ASYNC16(sKb + (uint32_t)(r * 36 + c4) * 4u, kb + (size_t)r * CQK + c4);
    }
#pragma unroll
    for (int i = 0; i < 8; i++) {
        int idx = t + i * 512;
        int r = idx >> 4, c4 = (idx & 15) * 4;
        CP_ASYNC16(sVb + (uint32_t)(r * 68 + c4) * 4u, vb + (size_t)r * NNp + c4);
    }
    CP_COMMIT(); CP_WAIT(0); __syncthreads();

    // hoist Q fragments (loop-invariant)
    uint32_t afrQ[2][4][4];
#pragma unroll
    for (int mf = 0; mf < 2; mf++)
#pragma unroll
        for (int ks = 0; ks < 4; ks++)
            lda_frag(afrQ[mf][ks], sQ + (wm * 32 + mf * 16 + gr) * 36 + ks * 8 + gc, 36);

    float O[2][8][4];
#pragma unroll
    for (int mf = 0; mf < 2; mf++)
#pragma unroll
        for (int cf = 0; cf < 8; cf++)
#pragma unroll
            for (int j = 0; j < 4; j++) O[mf][cf][j] = 0.f;

    float rsum[2][2] = {{0.f, 0.f}, {0.f, 0.f}};

    for (int it = 0; it < 64; it++) {
        const int buf = it & 1;
        const uint32_t sKbase = sKb + (uint32_t)(buf * 64 * 36) * 4u + kOff;
        const uint32_t sVbase = sVb + (uint32_t)(buf * 256 * 68) * 4u + vOff;

        // prefetch K(it+1), V(it+1)
        if (it + 1 < 64) {
            {
                const float* src = kb + (size_t)(it + 1) * 64 * CQK;
                int r = t >> 3, c4 = (t & 7) * 4;
                CP_ASYNC16(sKb + (uint32_t)((buf ^ 1) * 64 * 36 + r * 36 + c4) * 4u,
                           src + (size_t)r * CQK + c4);
            }
            {
                const float* src = vb + (size_t)(it + 1) * 64;
                uint32_t dstb = sVb + (uint32_t)((buf ^ 1) * 256 * 68) * 4u;
#pragma unroll
                for (int i = 0; i < 8; i++) {
                    int idx = t + i * 512;
                    int r = idx >> 4, c4 = (idx & 15) * 4;
                    CP_ASYNC16(dstb + (uint32_t)(r * 68 + c4) * 4u,
                               src + (size_t)r * NNp + c4);
                }
            }
            CP_COMMIT();
        }

        // S = Q x K(it)^T : warp 32m x 16n
        float sacc[2][2][4];
#pragma unroll
        for (int mf = 0; mf < 2; mf++)
#pragma unroll
            for (int nf = 0; nf < 2; nf++)
#pragma unroll
                for (int j = 0; j < 4; j++) sacc[mf][nf][j] = 0.f;
#pragma unroll
        for (int ks = 0; ks < 4; ks++) {
            uint32_t bfr[4];
            ldsm_x4(bfr, sKbase + (uint32_t)(ks * 8) * 4u);
#pragma unroll
            for (int mf = 0; mf < 2; mf++) {
                mma_tf32(sacc[mf][0], afrQ[mf][ks], bfr);
                mma_tf32(sacc[mf][1], afrQ[mf][ks], bfr + 2);
            }
        }

        // P = 2^S (unnormalized), accumulate row sums, stage to sP
#pragma unroll
        for (int mf = 0; mf < 2; mf++)
#pragma unroll
            for (int half = 0; half < 2; half++) {
                const int row = wm * 32 + mf * 16 + half * 8 + gr;
                float part = 0.f;
#pragma unroll
                for (int nf = 0; nf < 2; nf++) {
                    const int col = qn * 16 + nf * 8 + gc * 2;
                    float p0 = ex2f(sacc[mf][nf][half * 2]);
                    float p1 = ex2f(sacc[mf][nf][half * 2 + 1]);
                    part += p0 + p1;
                    *(float2*)&sP[row * 68 + col] = make_float2(p0, p1);
                }
                rsum[mf][half] += part;
            }
        __syncthreads();   // publish P

        // O += P x V(it)^T : warp 32m x 64c
#pragma unroll
        for (int ks = 0; ks < 8; ks++) {
            uint32_t afr[2][4], bfr[4][4];
            ldsm_x4(afr[0], sPb + pOff0 + (uint32_t)(ks * 8) * 4u);
            ldsm_x4(afr[1], sPb + pOff0 + (uint32_t)(16 * 68 + ks * 8) * 4u);
#pragma unroll
            for (int cfp = 0; cfp < 4; cfp++)
                ldsm_x4(bfr[cfp], sVbase + (uint32_t)(cfp * 16 * 68 + ks * 8) * 4u);
#pragma unroll
            for (int mf = 0; mf < 2; mf++)
#pragma unroll
                for (int cfp = 0; cfp < 4; cfp++) {
                    mma_tf32(O[mf][cfp * 2],     afr[mf], bfr[cfp]);
                    mma_tf32(O[mf][cfp * 2 + 1], afr[mf], bfr[cfp] + 2);
                }
        }

        if (it + 1 < 64) { CP_WAIT(0); }
        __syncthreads();
    }

    // row-sum reduction across quadrants
#pragma unroll
    for (int mf = 0; mf < 2; mf++)
#pragma unroll
        for (int half = 0; half < 2; half++) {
            float r = rsum[mf][half];
            r += __shfl_xor_sync(0xffffffffu, r, 1);
            r += __shfl_xor_sync(0xffffffffu, r, 2);
            if (gc == 0)
                sSum[(wm * 32 + mf * 16 + half * 8 + gr) * 4 + qn] = r;
        }
    __syncthreads();

    // epilogue: normalize + write O (tf32-rounded)
    float* ob = o + (size_t)b * NNp * CC + (size_t)m0 * CC;
#pragma unroll
    for (int mf = 0; mf < 2; mf++) {
        const int r0 = wm * 32 + mf * 16 + gr;
        const int r1 = r0 + 8;
        const float inv0 = 1.f / (sSum[r0 * 4] + sSum[r0 * 4 + 1] +
                                  sSum[r0 * 4 + 2] + sSum[r0 * 4 + 3]);
        const float inv1 = 1.f / (sSum[r1 * 4] + sSum[r1 * 4 + 1] +
                                  sSum[r1 * 4 + 2] + sSum[r1 * 4 + 3]);
#pragma unroll
        for (int cf = 0; cf < 8; cf++) {
            const int c = qn * 64 + cf * 8 + gc * 2;
            *(float2*)&ob[(size_t)r0 * CC + c] =
                make_float2(tf32r(O[mf][cf][0] * inv0), tf32r(O[mf][cf][1] * inv0));
            *(float2*)&ob[(size_t)r1 * CC + c] =
                make_float2(tf32r(O[mf][cf][2] * inv1), tf32r(O[mf][cf][3] * inv1));
        }
    }
}

// ---------------- prep: qk projection only ----------------------------------
__global__ void __launch_bounds__(256) qk_prep(
    const float* __restrict__ x,
    const float* __restrict__ Wq, const float* __restrict__ bq,
    const float* __restrict__ Wk, const float* __restrict__ bk,
    float* __restrict__ q, float* __restrict__ ko)
{
    __shared__ float sbuf[6144];
    const int bid = blockIdx.x;
    const int t = threadIdx.x;

    const int m0 = (bid & 31) * 128;
    const int b  = bid >> 5;
    const float* xb = x + (size_t)b * CC * NNp;
    float (*sx)[128] = (float(*)[128])sbuf;
    float (*sw)[32]  = (float(*)[32])(sbuf + 4096);

    const int mi   = t & 127;
    const int half = t >> 7;

    float acc[32];
    const float* bias = half ? bk : bq;
#pragma unroll
    for (int j = 0; j < 32; j++) acc[j] = bias[j];

    for (int c0 = 0; c0 < CC; c0 += 32) {
#pragma unroll
        for (int i = 0; i < 16; i++) {
            int idx = t + i * 256;
            int r = idx >> 7, mm = idx & 127;
            sx[r][mm] = xb[(size_t)(c0 + r) * NNp + m0 + mm];
        }
#pragma unroll
        for (int i = 0; i < 8; i++) {
            int idx = t + i * 256;
            int co = idx >> 5, cc = idx & 31;
            sw[co][cc] = (co < 32) ? Wq[co * 256 + c0 + cc]
                                   : Wk[(co - 32) * 256 + c0 + cc];
        }
        __syncthreads();
#pragma unroll
        for (int cc = 0; cc < 32; cc++) {
            float xv = sx[cc][mi];
#pragma unroll
            for (int j = 0; j < 32; j++) acc[j] += sw[half * 32 + j][cc] * xv;
        }
        __syncthreads();
    }

    const float scl = half ? 1.f : 1.4426950408889634f;
    float* dst = (half ? ko : q) + (size_t)b * NNp * CQK + (size_t)(m0 + mi) * CQK;
#pragma unroll
    for (int j = 0; j < 32; j += 4)
        *(float4*)&dst[j] = make_float4(tf32r(acc[j] * scl), tf32r(acc[j + 1] * scl),
                                        tf32r(acc[j + 2] * scl), tf32r(acc[j + 3] * scl));
}

// ---------------- launch ----------------
extern "C" void kernel_launch(void* const* d_in, const int* in_sizes, int n_in,
                              void* d_out, int out_size)
{
    const float* x  = (const float*)d_in[0];
    const float* Wq = (const float*)d_in[1];
    const float* bq = (const float*)d_in[2];
    const float* Wk = (const float*)d_in[3];
    const float* bk = (const float*)d_in[4];
    const float* Wv = (const float*)d_in[5];
    const float* bv = (const float*)d_in[6];
    const float* Wo = (const float*)d_in[7];
    const float* bo = (const float*)d_in[8];
    float* y = (float*)d_out;

    float *p_q, *p_k, *p_v, *p_o;
    cudaGetSymbolAddress((void**)&p_q,  g_q);
    cudaGetSymbolAddress((void**)&p_k,  g_k);
    cudaGetSymbolAddress((void**)&p_v,  g_v);
    cudaGetSymbolAddress((void**)&p_o,  g_o);

    const size_t sX = (size_t)CC * NNp;

    const int SMEM_G = 4 * TILE_F * 4;
    cudaFuncSetAttribute(tc_gemm, cudaFuncAttributeMaxDynamicSharedMemorySize, SMEM_G);
    const int SMEM_B = SMB_F * 4;
    cudaFuncSetAttribute(attn_pv, cudaFuncAttributeMaxDynamicSharedMemorySize, SMEM_B);

    // prep: qk projection only (weights rounded in-fragment in tc_gemm now)
    qk_prep<<<128, 256>>>(x, Wq, bq, Wk, bk, p_q, p_k);

    // v[c][n] = Wv @ x + bv  (A = raw Wv, B = x transposed mode)
    tc_gemm<<<dim3(NNp / 128, CC / 128, BB), 256, SMEM_G>>>(
        Wv, CC, 0,
        x, NNp, sX, 1,
        nullptr, 0, 0, 0, CC,
        p_v, NNp, sX,
        bv, CC, 1);

    // single-pass fused attention -> g_o [m][c]
    attn_pv<<<dim3(NNp / 128, 1, BB), 512, SMEM_B>>>(p_q, p_k, p_v, p_o);

    // y = Wo @ concat(o, x)^T + bo  (A = raw Wo; B1 = o natural, B2 = x transposed)
    tc_gemm<<<dim3(NNp / 128, CC / 128, BB), 256, SMEM_G>>>(
        Wo, 2 * CC, 0,
        p_o, CC, sX, 0,
        x, NNp, sX, 1, CC,
        y, NNp, sX,
        bo, 2 * CC, 0);
}

// round 16
// speedup vs baseline: 1.1522x; 1.0173x over previous
#include <cuda_runtime.h>
#include <cstdint>
#include <math.h>

// Problem constants
#define BB   4
#define CC   256
#define CQK  32
#define NNp  4096

// ---------------- scratch ----------------
__device__ float  g_q [(size_t)BB * NNp * CQK];   // [b][m][32]  K-major, tf32, *log2e
__device__ float  g_k [(size_t)BB * NNp * CQK];   // [b][n][32]  K-major, tf32
__device__ float  g_v [(size_t)BB * CC * NNp];    // [b][c][n]   tf32
__device__ float  g_o [(size_t)BB * NNp * CC];    // [b][m][c]   tf32

// ---------------- helpers ----------------
__device__ __forceinline__ float tf32r(float x) {
    uint32_t y;
    asm("cvt.rna.tf32.f32 %0, %1;" : "=r"(y) : "f"(x));
    return __uint_as_float(y);
}
__device__ __forceinline__ uint32_t tf32r_u(float x) {
    uint32_t y;
    asm("cvt.rna.tf32.f32 %0, %1;" : "=r"(y) : "f"(x));
    return y;
}
__device__ __forceinline__ uint32_t tf32r_r(uint32_t x) {
    uint32_t y;
    asm("cvt.rna.tf32.f32 %0, %1;" : "=r"(y) : "f"(__uint_as_float(x)));
    return y;
}

__device__ __forceinline__ float ex2f(float x) {
    float y;
    asm("ex2.approx.f32 %0, %1;" : "=f"(y) : "f"(x));
    return y;
}

__device__ __forceinline__ uint32_t smem_u32(const void* p) {
    uint32_t a;
    asm("{ .reg .u64 t; cvta.to.shared.u64 t, %1; cvt.u32.u64 %0, t; }"
        : "=r"(a) : "l"(p));
    return a;
}

#define CP_ASYNC16(dst, src) \
    asm volatile("cp.async.cg.shared.global [%0], [%1], 16;" :: "r"(dst), "l"(src))
#define CP_COMMIT() asm volatile("cp.async.commit_group;" ::: "memory")
#define CP_WAIT(n)  asm volatile("cp.async.wait_group %0;" :: "n"(n) : "memory")

__device__ __forceinline__ void mma_tf32(float* d, const uint32_t* a, const uint32_t* b) {
    asm volatile(
        "mma.sync.aligned.m16n8k8.row.col.f32.tf32.tf32.f32 "
        "{%0,%1,%2,%3}, {%4,%5,%6,%7}, {%8,%9}, {%0,%1,%2,%3};"
        : "+f"(d[0]), "+f"(d[1]), "+f"(d[2]), "+f"(d[3])
        : "r"(a[0]), "r"(a[1]), "r"(a[2]), "r"(a[3]), "r"(b[0]), "r"(b[1]));
}

__device__ __forceinline__ void ldsm_x4(uint32_t* r, uint32_t addr) {
    asm volatile("ldmatrix.sync.aligned.m8n8.x4.shared.b16 {%0,%1,%2,%3}, [%4];"
        : "=r"(r[0]), "=r"(r[1]), "=r"(r[2]), "=r"(r[3]) : "r"(addr));
}

__device__ __forceinline__ void lda_frag(uint32_t* a, const float* p, int str) {
    a[0] = __float_as_uint(p[0]);
    a[1] = __float_as_uint(p[8 * str]);
    a[2] = __float_as_uint(p[4]);
    a[3] = __float_as_uint(p[8 * str + 4]);
}

// ---------------- tf32 mma.sync GEMM (R15, unchanged) ------------------------
#define SROW 36
#define TILE_F (128 * SROW)
#define BTS 132

__global__ void __launch_bounds__(256, 2) tc_gemm(
    const float* __restrict__ A, int lda, size_t sAb,
    const float* __restrict__ B1, int ldb1, size_t sB1b, int bT1,
    const float* __restrict__ B2, int ldb2, size_t sB2b, int bT2, int ksplit,
    float* __restrict__ C, int ldc, size_t sCb,
    const float* __restrict__ bias, int K, int round_out)
{
    extern __shared__ float4 smem4[];
    float* sm = (float*)smem4;

    const int b = blockIdx.z;
    A  += (size_t)b * sAb;
    B1 += (size_t)b * sB1b;
    const float* B2p = B2 ? (B2 + (size_t)b * sB2b) : nullptr;
    C  += (size_t)b * sCb;

    const int n0 = blockIdx.x * 128;
    const int m0 = blockIdx.y * 128;
    const int t    = threadIdx.x;
    const int lane = t & 31;
    const int warp = t >> 5;
    const int wm = (warp & 3) * 32;
    const int wn = (warp >> 2) * 64;
    const int gr = lane >> 2;
    const int gc = lane & 3;

    const uint32_t sbase = smem_u32(sm);
    const int ldr = t >> 3;
    const int ldc4 = (t & 7) * 4;

    const uint32_t aOff = (uint32_t)((wm + (lane & 15)) * SROW + ((lane & 16) >> 2));
    const uint32_t bOff = (uint32_t)((wn + (lane & 7) + ((lane & 16) >> 1)) * SROW
                                     + ((lane & 8) >> 1));

    const int nk = K / 32;

    auto issue_tile = [&](int kb, int buf) {
        const int k0 = kb * 32;
        {
            const float* src = A + (size_t)(m0 + ldr) * lda + k0 + ldc4;
            uint32_t dst = sbase + (uint32_t)(buf * 2 * TILE_F) * 4u
                         + (uint32_t)(ldr * SROW + ldc4) * 4u;
#pragma unroll
            for (int i = 0; i < 4; i++)
                CP_ASYNC16(dst + (uint32_t)(i * 32 * SROW) * 4u,
                           src + (size_t)(i * 32) * lda);
        }
        {
            const float* Bp; int ldb, kk, bT;
            if (k0 < ksplit) { Bp = B1;  ldb = ldb1; kk = k0;          bT = bT1; }
            else             { Bp = B2p; ldb = ldb2; kk = k0 - ksplit; bT = bT2; }
            uint32_t bbase = sbase + (uint32_t)((buf * 2 + 1) * TILE_F) * 4u;
            if (bT) {
                const int r  = t >> 5;
                const int c4 = (t & 31) * 4;
                const float* src = Bp + (size_t)(kk + r) * ldb + n0 + c4;
#pragma unroll
                for (int i = 0; i < 4; i++)
                    CP_ASYNC16(bbase + (uint32_t)((r + i * 8) * BTS + c4) * 4u,
                               src + (size_t)(i * 8) * ldb);
            } else {
                const float* src = Bp + (size_t)(n0 + ldr) * ldb + kk + ldc4;
                uint32_t dst = bbase + (uint32_t)(ldr * SROW + ldc4) * 4u;
#pragma unroll
                for (int i = 0; i < 4; i++)
                    CP_ASYNC16(dst + (uint32_t)(i * 32 * SROW) * 4u,
                               src + (size_t)(i * 32) * ldb);
            }
        }
        CP_COMMIT();
    };

    float acc[2][8][4];
#pragma unroll
    for (int mf = 0; mf < 2; mf++)
#pragma unroll
        for (int nf = 0; nf < 8; nf++)
#pragma unroll
            for (int j = 0; j < 4; j++) acc[mf][nf][j] = 0.f;

    issue_tile(0, 0);

    for (int kb = 0; kb < nk; kb++) {
        const int buf = kb & 1;
        if (kb + 1 < nk) { issue_tile(kb + 1, buf ^ 1); CP_WAIT(1); }
        else             { CP_WAIT(0); }
        __syncthreads();

        const uint32_t sAu = sbase + (uint32_t)(buf * 2 * TILE_F) * 4u;
        const uint32_t sBu = sAu + (uint32_t)TILE_F * 4u;
        const float* sB = sm + (buf * 2 + 1) * TILE_F;
        const int modeT = (kb * 32 < ksplit) ? bT1 : bT2;

#pragma unroll
        for (int ks = 0; ks < 4; ks++) {
            const int k0 = ks * 8;
            uint32_t afr[2][4];
#pragma unroll
            for (int mf = 0; mf < 2; mf++) {
                ldsm_x4(afr[mf], sAu + (aOff + (uint32_t)(mf * 16 * SROW + k0)) * 4u);
#pragma unroll
                for (int j = 0; j < 4; j++) afr[mf][j] = tf32r_r(afr[mf][j]);
            }
            if (modeT) {
                uint32_t bfr[8][2];
#pragma unroll
                for (int nf = 0; nf < 8; nf++) {
                    const int nn = wn + nf * 8 + gr;
                    bfr[nf][0] = tf32r_u(sB[(k0 + gc) * BTS + nn]);
                    bfr[nf][1] = tf32r_u(sB[(k0 + gc + 4) * BTS + nn]);
                }
#pragma unroll
                for (int mf = 0; mf < 2; mf++)
#pragma unroll
                    for (int nf = 0; nf < 8; nf++)
                        mma_tf32(acc[mf][nf], afr[mf], bfr[nf]);
            } else {
                uint32_t bfr[4][4];
#pragma unroll
                for (int nfp = 0; nfp < 4; nfp++)
                    ldsm_x4(bfr[nfp], sBu + (bOff + (uint32_t)(nfp * 16 * SROW + k0)) * 4u);
#pragma unroll
                for (int mf = 0; mf < 2; mf++)
#pragma unroll
                    for (int nfp = 0; nfp < 4; nfp++) {
                        mma_tf32(acc[mf][nfp * 2],     afr[mf], bfr[nfp]);
                        mma_tf32(acc[mf][nfp * 2 + 1], afr[mf], bfr[nfp] + 2);
                    }
            }
        }
        __syncthreads();
    }

#pragma unroll
    for (int mf = 0; mf < 2; mf++) {
        const int m = m0 + wm + mf * 16 + gr;
        const float bi0 = bias ? bias[m]     : 0.f;
        const float bi1 = bias ? bias[m + 8] : 0.f;
#pragma unroll
        for (int nf = 0; nf < 8; nf++) {
            const int n = n0 + wn + nf * 8 + gc * 2;
            float2 r0, r1;
            r0.x = acc[mf][nf][0] + bi0; r0.y = acc[mf][nf][1] + bi0;
            r1.x = acc[mf][nf][2] + bi1; r1.y = acc[mf][nf][3] + bi1;
            if (round_out) {
                r0.x = tf32r(r0.x); r0.y = tf32r(r0.y);
                r1.x = tf32r(r1.x); r1.y = tf32r(r1.y);
            }
            *(float2*)&C[(size_t)m * ldc + n]       = r0;
            *(float2*)&C[(size_t)(m + 8) * ldc + n] = r1;
        }
    }
}

// ---------------- fused attention, software-pipelined (1 sync/iter) ----------
// grid (32, 1, 4), 512 threads (16 warps: 4 wm x 4 qn). m-tile 128, n-tile 64.
// Iter it: prefetch K(it+2),V(it+1); S(it+1); ex2->sP[^1]; PV(it); wait+sync.
// sP double-buffered; sP[1] overlays Q's staging (Q hoisted to regs first).
#define OP1 0                            // P buf 1: 128*68 = 8704 f (Q stages here)
#define OKB 8704                         // K: 2 x 64*36 = 4608 f
#define OP0 13312                        // P buf 0: 8704 f
#define OVB 22016                        // V: 2 x 256*68 = 34816 f
#define OSUM 56832                       // 512 f
#define SMB_F 57344                      // 229376 B

__global__ void __launch_bounds__(512) attn_pv(
    const float* __restrict__ q, const float* __restrict__ k,
    const float* __restrict__ v, float* __restrict__ o)
{
    extern __shared__ float smf[];
    float* sQ = smf + OP1;               // staging only (overlaid by sP[1])
    float* sK = smf + OKB;
    float* sV = smf + OVB;
    float* sSum = smf + OSUM;
    float* sPb0 = smf + OP0;
    float* sPb1 = smf + OP1;

    const int b  = blockIdx.z;
    const int m0 = blockIdx.x * 128;
    const float* qb = q + (size_t)b * NNp * CQK + (size_t)m0 * CQK;
    const float* kb = k + (size_t)b * NNp * CQK;
    const float* vb = v + (size_t)b * CC * NNp;

    const int t = threadIdx.x;
    const int lane = t & 31, warp = t >> 5;
    const int wm = warp & 3;
    const int qn = warp >> 2;
    const int gr = lane >> 2, gc = lane & 3;

    const uint32_t sQb = smem_u32(sQ), sKb = smem_u32(sK), sVb = smem_u32(sV);
    const uint32_t sP0u = smem_u32(sPb0), sP1u = smem_u32(sPb1);

    const uint32_t kOff = (uint32_t)((qn * 16 + (lane & 7) + ((lane & 16) >> 1)) * 36
                                     + ((lane & 8) >> 1)) * 4u;
    const uint32_t pOff0 = (uint32_t)((wm * 32 + (lane & 15)) * 68
                                      + ((lane & 16) >> 2)) * 4u;
    const uint32_t vOff = (uint32_t)((qn * 64 + (lane & 7) + ((lane & 16) >> 1)) * 68
                                     + ((lane & 8) >> 1)) * 4u;

    // ---- prologue: Q, K(0), K(1), V(0) ----
#pragma unroll
    for (int i = 0; i < 2; i++) {
        int idx = t + i * 512;
        int r = idx >> 3, c4 = (idx & 7) * 4;
        CP_ASYNC16(sQb + (uint32_t)(r * 36 + c4) * 4u, qb + (size_t)r * CQK + c4);
    }
    {
        int r = t >> 3, c4 = (t & 7) * 4;
        CP_ASYNC16(sKb + (uint32_t)(r * 36 + c4) * 4u, kb + (size_t)r * CQK + c4);
        CP_ASYNC16(sKb + (uint32_t)(64 * 36 + r * 36 + c4) * 4u,
                   kb + (size_t)(64 + r) * CQK + c4);
    }
#pragma unroll
    for (int i = 0; i < 8; i++) {
        int idx = t + i * 512;
        int r = idx >> 4, c4 = (idx & 15) * 4;
        CP_ASYNC16(sVb + (uint32_t)(r * 68 + c4) * 4u, vb + (size_t)r * NNp + c4);
    }
    CP_COMMIT(); CP_WAIT(0); __syncthreads();

    // hoist Q fragments to registers (frees sQ region for sP[1])
    uint32_t afrQ[2][4][4];
#pragma unroll
    for (int mf = 0; mf < 2; mf++)
#pragma unroll
        for (int ks = 0; ks < 4; ks++)
            lda_frag(afrQ[mf][ks], sQ + (wm * 32 + mf * 16 + gr) * 36 + ks * 8 + gc, 36);
    __syncthreads();   // all warps done reading sQ before sP[1] writes

    float O[2][8][4];
#pragma unroll
    for (int mf = 0; mf < 2; mf++)
#pragma unroll
        for (int cf = 0; cf < 8; cf++)
#pragma unroll
            for (int j = 0; j < 4; j++) O[mf][cf][j] = 0.f;

    float rsum[2][2] = {{0.f, 0.f}, {0.f, 0.f}};

    // S(0) -> P(0) into sP[0]
    {
        float sacc[2][2][4];
#pragma unroll
        for (int mf = 0; mf < 2; mf++)
#pragma unroll
            for (int nf = 0; nf < 2; nf++)
#pragma unroll
                for (int j = 0; j < 4; j++) sacc[mf][nf][j] = 0.f;
#pragma unroll
        for (int ks = 0; ks < 4; ks++) {
            uint32_t bfr[4];
            ldsm_x4(bfr, sKb + kOff + (uint32_t)(ks * 8) * 4u);
#pragma unroll
            for (int mf = 0; mf < 2; mf++) {
                mma_tf32(sacc[mf][0], afrQ[mf][ks], bfr);
                mma_tf32(sacc[mf][1], afrQ[mf][ks], bfr + 2);
            }
        }
#pragma unroll
        for (int mf = 0; mf < 2; mf++)
#pragma unroll
            for (int half = 0; half < 2; half++) {
                const int row = wm * 32 + mf * 16 + half * 8 + gr;
                float part = 0.f;
#pragma unroll
                for (int nf = 0; nf < 2; nf++) {
                    const int col = qn * 16 + nf * 8 + gc * 2;
                    float p0 = ex2f(sacc[mf][nf][half * 2]);
                    float p1 = ex2f(sacc[mf][nf][half * 2 + 1]);
                    part += p0 + p1;
                    *(float2*)&sPb0[row * 68 + col] = make_float2(p0, p1);
                }
                rsum[mf][half] += part;
            }
    }
    __syncthreads();   // publish P(0)

    // ---- main loop: 1 sync per iteration ----
    for (int it = 0; it < 64; it++) {
        const int buf = it & 1;
        const uint32_t sPrd = buf ? sP1u : sP0u;   // P(it)
        const uint32_t sVbase = sVb + (uint32_t)(buf * 256 * 68) * 4u + vOff;

        // 0. prefetch K(it+2) -> sK[it&1], V(it+1) -> sV[buf^1]
        if (it + 1 < 64) {
            if (it + 2 < 64) {
                const float* src = kb + (size_t)(it + 2) * 64 * CQK;
                int r = t >> 3, c4 = (t & 7) * 4;
                CP_ASYNC16(sKb + (uint32_t)(buf * 64 * 36 + r * 36 + c4) * 4u,
                           src + (size_t)r * CQK + c4);
            }
            {
                const float* src = vb + (size_t)(it + 1) * 64;
                uint32_t dstb = sVb + (uint32_t)((buf ^ 1) * 256 * 68) * 4u;
#pragma unroll
                for (int i = 0; i < 8; i++) {
                    int idx = t + i * 512;
                    int r = idx >> 4, c4 = (idx & 15) * 4;
                    CP_ASYNC16(dstb + (uint32_t)(r * 68 + c4) * 4u,
                               src + (size_t)r * NNp + c4);
                }
            }
            CP_COMMIT();
        }

        // 1-2. S(it+1) from sK[(it+1)&1]; ex2 -> sP[buf^1]
        if (it + 1 < 64) {
            const uint32_t sKbase = sKb + (uint32_t)(((it + 1) & 1) * 64 * 36) * 4u + kOff;
            float sacc[2][2][4];
#pragma unroll
            for (int mf = 0; mf < 2; mf++)
#pragma unroll
                for (int nf = 0; nf < 2; nf++)
#pragma unroll
                    for (int j = 0; j < 4; j++) sacc[mf][nf][j] = 0.f;
#pragma unroll
            for (int ks = 0; ks < 4; ks++) {
                uint32_t bfr[4];
                ldsm_x4(bfr, sKbase + (uint32_t)(ks * 8) * 4u);
#pragma unroll
                for (int mf = 0; mf < 2; mf++) {
                    mma_tf32(sacc[mf][0], afrQ[mf][ks], bfr);
                    mma_tf32(sacc[mf][1], afrQ[mf][ks], bfr + 2);
                }
            }
            float* sPwr = buf ? sPb0 : sPb1;   // sP[buf^1]
#pragma unroll
            for (int mf = 0; mf < 2; mf++)
#pragma unroll
                for (int half = 0; half < 2; half++) {
                    const int row = wm * 32 + mf * 16 + half * 8 + gr;
                    float part = 0.f;
#pragma unroll
                    for (int nf = 0; nf < 2; nf++) {
                        const int col = qn * 16 + nf * 8 + gc * 2;
                        float p0 = ex2f(sacc[mf][nf][half * 2]);
                        float p1 = ex2f(sacc[mf][nf][half * 2 + 1]);
                        part += p0 + p1;
                        *(float2*)&sPwr[row * 68 + col] = make_float2(p0, p1);
                    }
                    rsum[mf][half] += part;
                }
        }

        // 3. PV(it) from sP[buf], sV[buf]
#pragma unroll
        for (int ks = 0; ks < 8; ks++) {
            uint32_t afr[2][4], bfr[4][4];
            ldsm_x4(afr[0], sPrd + pOff0 + (uint32_t)(ks * 8) * 4u);
            ldsm_x4(afr[1], sPrd + pOff0 + (uint32_t)(16 * 68 + ks * 8) * 4u);
#pragma unroll
            for (int cfp = 0; cfp < 4; cfp++)
                ldsm_x4(bfr[cfp], sVbase + (uint32_t)(cfp * 16 * 68 + ks * 8) * 4u);
#pragma unroll
            for (int mf = 0; mf < 2; mf++)
#pragma unroll
                for (int cfp = 0; cfp < 4; cfp++) {
                    mma_tf32(O[mf][cfp * 2],     afr[mf], bfr[cfp]);
                    mma_tf32(O[mf][cfp * 2 + 1], afr[mf], bfr[cfp] + 2);
                }
        }

        // 4. single barrier: publishes P(it+1) and K/V prefetch; orders WARs
        if (it + 1 < 64) { CP_WAIT(0); }
        __syncthreads();
    }

    // row-sum reduction across quadrants
#pragma unroll
    for (int mf = 0; mf < 2; mf++)
#pragma unroll
        for (int half = 0; half < 2; half++) {
            float r = rsum[mf][half];
            r += __shfl_xor_sync(0xffffffffu, r, 1);
            r += __shfl_xor_sync(0xffffffffu, r, 2);
            if (gc == 0)
                sSum[(wm * 32 + mf * 16 + half * 8 + gr) * 4 + qn] = r;
        }
    __syncthreads();

    // epilogue: normalize + write O (tf32-rounded)
    float* ob = o + (size_t)b * NNp * CC + (size_t)m0 * CC;
#pragma unroll
    for (int mf = 0; mf < 2; mf++) {
        const int r0 = wm * 32 + mf * 16 + gr;
        const int r1 = r0 + 8;
        const float inv0 = 1.f / (sSum[r0 * 4] + sSum[r0 * 4 + 1] +
                                  sSum[r0 * 4 + 2] + sSum[r0 * 4 + 3]);
        const float inv1 = 1.f / (sSum[r1 * 4] + sSum[r1 * 4 + 1] +
                                  sSum[r1 * 4 + 2] + sSum[r1 * 4 + 3]);
#pragma unroll
        for (int cf = 0; cf < 8; cf++) {
            const int c = qn * 64 + cf * 8 + gc * 2;
            *(float2*)&ob[(size_t)r0 * CC + c] =
                make_float2(tf32r(O[mf][cf][0] * inv0), tf32r(O[mf][cf][1] * inv0));
            *(float2*)&ob[(size_t)r1 * CC + c] =
                make_float2(tf32r(O[mf][cf][2] * inv1), tf32r(O[mf][cf][3] * inv1));
        }
    }
}

// ---------------- prep: qk projection only ----------------------------------
__global__ void __launch_bounds__(256) qk_prep(
    const float* __restrict__ x,
    const float* __restrict__ Wq, const float* __restrict__ bq,
    const float* __restrict__ Wk, const float* __restrict__ bk,
    float* __restrict__ q, float* __restrict__ ko)
{
    __shared__ float sbuf[6144];
    const int bid = blockIdx.x;
    const int t = threadIdx.x;

    const int m0 = (bid & 31) * 128;
    const int b  = bid >> 5;
    const float* xb = x + (size_t)b * CC * NNp;
    float (*sx)[128] = (float(*)[128])sbuf;
    float (*sw)[32]  = (float(*)[32])(sbuf + 4096);

    const int mi   = t & 127;
    const int half = t >> 7;

    float acc[32];
    const float* bias = half ? bk : bq;
#pragma unroll
    for (int j = 0; j < 32; j++) acc[j] = bias[j];

    for (int c0 = 0; c0 < CC; c0 += 32) {
#pragma unroll
        for (int i = 0; i < 16; i++) {
            int idx = t + i * 256;
            int r = idx >> 7, mm = idx & 127;
            sx[r][mm] = xb[(size_t)(c0 + r) * NNp + m0 + mm];
        }
#pragma unroll
        for (int i = 0; i < 8; i++) {
            int idx = t + i * 256;
            int co = idx >> 5, cc = idx & 31;
            sw[co][cc] = (co < 32) ? Wq[co * 256 + c0 + cc]
                                   : Wk[(co - 32) * 256 + c0 + cc];
        }
        __syncthreads();
#pragma unroll
        for (int cc = 0; cc < 32; cc++) {
            float xv = sx[cc][mi];
#pragma unroll
            for (int j = 0; j < 32; j++) acc[j] += sw[half * 32 + j][cc] * xv;
        }
        __syncthreads();
    }

    const float scl = half ? 1.f : 1.4426950408889634f;
    float* dst = (half ? ko : q) + (size_t)b * NNp * CQK + (size_t)(m0 + mi) * CQK;
#pragma unroll
    for (int j = 0; j < 32; j += 4)
        *(float4*)&dst[j] = make_float4(tf32r(acc[j] * scl), tf32r(acc[j + 1] * scl),
                                        tf32r(acc[j + 2] * scl), tf32r(acc[j + 3] * scl));
}

// ---------------- launch ----------------
extern "C" void kernel_launch(void* const* d_in, const int* in_sizes, int n_in,
                              void* d_out, int out_size)
{
    const float* x  = (const float*)d_in[0];
    const float* Wq = (const float*)d_in[1];
    const float* bq = (const float*)d_in[2];
    const float* Wk = (const float*)d_in[3];
    const float* bk = (const float*)d_in[4];
    const float* Wv = (const float*)d_in[5];
    const float* bv = (const float*)d_in[6];
    const float* Wo = (const float*)d_in[7];
    const float* bo = (const float*)d_in[8];
    float* y = (float*)d_out;

    float *p_q, *p_k, *p_v, *p_o;
    cudaGetSymbolAddress((void**)&p_q,  g_q);
    cudaGetSymbolAddress((void**)&p_k,  g_k);
    cudaGetSymbolAddress((void**)&p_v,  g_v);
    cudaGetSymbolAddress((void**)&p_o,  g_o);

    const size_t sX = (size_t)CC * NNp;

    const int SMEM_G = 4 * TILE_F * 4;
    cudaFuncSetAttribute(tc_gemm, cudaFuncAttributeMaxDynamicSharedMemorySize, SMEM_G);
    const int SMEM_B = SMB_F * 4;   // 229376 B
    cudaFuncSetAttribute(attn_pv, cudaFuncAttributeMaxDynamicSharedMemorySize, SMEM_B);

    // prep: qk projection only
    qk_prep<<<128, 256>>>(x, Wq, bq, Wk, bk, p_q, p_k);

    // v[c][n] = Wv @ x + bv  (A = raw Wv, B = x transposed mode)
    tc_gemm<<<dim3(NNp / 128, CC / 128, BB), 256, SMEM_G>>>(
        Wv, CC, 0,
        x, NNp, sX, 1,
        nullptr, 0, 0, 0, CC,
        p_v, NNp, sX,
        bv, CC, 1);

    // software-pipelined fused attention -> g_o [m][c]
    attn_pv<<<dim3(NNp / 128, 1, BB), 512, SMEM_B>>>(p_q, p_k, p_v, p_o);

    // y = Wo @ concat(o, x)^T + bo
    tc_gemm<<<dim3(NNp / 128, CC / 128, BB), 256, SMEM_G>>>(
        Wo, 2 * CC, 0,
        p_o, CC, sX, 0,
        x, NNp, sX, 1, CC,
        y, NNp, sX,
        bo, 2 * CC, 0);
}

// round 17
// speedup vs baseline: 1.6858x; 1.4632x over previous
#include <cuda_runtime.h>
#include <cuda_fp16.h>
#include <cstdint>
#include <math.h>

// Problem constants
#define BB   4
#define CC   256
#define CQK  32
#define NNp  4096

// ---------------- scratch ----------------
__device__ float  g_q [(size_t)BB * NNp * CQK];   // [b][m][32]  K-major, tf32, *log2e
__device__ float  g_k [(size_t)BB * NNp * CQK];   // [b][n][32]  K-major, tf32
__device__ __half g_v [(size_t)BB * CC * NNp];    // [b][c][n]   fp16
__device__ float  g_o [(size_t)BB * NNp * CC];    // [b][m][c]   tf32

// ---------------- helpers ----------------
__device__ __forceinline__ float tf32r(float x) {
    uint32_t y;
    asm("cvt.rna.tf32.f32 %0, %1;" : "=r"(y) : "f"(x));
    return __uint_as_float(y);
}
__device__ __forceinline__ uint32_t tf32r_u(float x) {
    uint32_t y;
    asm("cvt.rna.tf32.f32 %0, %1;" : "=r"(y) : "f"(x));
    return y;
}
__device__ __forceinline__ uint32_t tf32r_r(uint32_t x) {
    uint32_t y;
    asm("cvt.rna.tf32.f32 %0, %1;" : "=r"(y) : "f"(__uint_as_float(x)));
    return y;
}

__device__ __forceinline__ float ex2f(float x) {
    float y;
    asm("ex2.approx.f32 %0, %1;" : "=f"(y) : "f"(x));
    return y;
}

// pack two floats to half2: lo = second arg, hi = first arg
__device__ __forceinline__ uint32_t h2_rn(float hi, float lo) {
    uint32_t d;
    asm("cvt.rn.f16x2.f32 %0, %1, %2;" : "=r"(d) : "f"(hi), "f"(lo));
    return d;
}

__device__ __forceinline__ uint32_t smem_u32(const void* p) {
    uint32_t a;
    asm("{ .reg .u64 t; cvta.to.shared.u64 t, %1; cvt.u32.u64 %0, t; }"
        : "=r"(a) : "l"(p));
    return a;
}

#define CP_ASYNC16(dst, src) \
    asm volatile("cp.async.cg.shared.global [%0], [%1], 16;" :: "r"(dst), "l"(src))
#define CP_COMMIT() asm volatile("cp.async.commit_group;" ::: "memory")
#define CP_WAIT(n)  asm volatile("cp.async.wait_group %0;" :: "n"(n) : "memory")

__device__ __forceinline__ void mma_tf32(float* d, const uint32_t* a, const uint32_t* b) {
    asm volatile(
        "mma.sync.aligned.m16n8k8.row.col.f32.tf32.tf32.f32 "
        "{%0,%1,%2,%3}, {%4,%5,%6,%7}, {%8,%9}, {%0,%1,%2,%3};"
        : "+f"(d[0]), "+f"(d[1]), "+f"(d[2]), "+f"(d[3])
        : "r"(a[0]), "r"(a[1]), "r"(a[2]), "r"(a[3]), "r"(b[0]), "r"(b[1]));
}

__device__ __forceinline__ void mma_f16(float* d, const uint32_t* a, const uint32_t* b) {
    asm volatile(
        "mma.sync.aligned.m16n8k16.row.col.f32.f16.f16.f32 "
        "{%0,%1,%2,%3}, {%4,%5,%6,%7}, {%8,%9}, {%0,%1,%2,%3};"
        : "+f"(d[0]), "+f"(d[1]), "+f"(d[2]), "+f"(d[3])
        : "r"(a[0]), "r"(a[1]), "r"(a[2]), "r"(a[3]), "r"(b[0]), "r"(b[1]));
}

__device__ __forceinline__ void ldsm_x4(uint32_t* r, uint32_t addr) {
    asm volatile("ldmatrix.sync.aligned.m8n8.x4.shared.b16 {%0,%1,%2,%3}, [%4];"
        : "=r"(r[0]), "=r"(r[1]), "=r"(r[2]), "=r"(r[3]) : "r"(addr));
}

__device__ __forceinline__ void lda_frag(uint32_t* a, const float* p, int str) {
    a[0] = __float_as_uint(p[0]);
    a[1] = __float_as_uint(p[8 * str]);
    a[2] = __float_as_uint(p[4]);
    a[3] = __float_as_uint(p[8 * str + 4]);
}

// ---------------- tf32 mma.sync GEMM ------------------------------------------
// out_mode: 0 = fp32 raw, 1 = fp32 tf32-rounded, 2 = fp16 half2 (C cast to half*)
#define SROW 36
#define TILE_F (128 * SROW)
#define BTS 132

__global__ void __launch_bounds__(256, 2) tc_gemm(
    const float* __restrict__ A, int lda, size_t sAb,
    const float* __restrict__ B1, int ldb1, size_t sB1b, int bT1,
    const float* __restrict__ B2, int ldb2, size_t sB2b, int bT2, int ksplit,
    float* __restrict__ C, int ldc, size_t sCb,
    const float* __restrict__ bias, int K, int out_mode)
{
    extern __shared__ float4 smem4[];
    float* sm = (float*)smem4;

    const int b = blockIdx.z;
    A  += (size_t)b * sAb;
    B1 += (size_t)b * sB1b;
    const float* B2p = B2 ? (B2 + (size_t)b * sB2b) : nullptr;

    const int n0 = blockIdx.x * 128;
    const int m0 = blockIdx.y * 128;
    const int t    = threadIdx.x;
    const int lane = t & 31;
    const int warp = t >> 5;
    const int wm = (warp & 3) * 32;
    const int wn = (warp >> 2) * 64;
    const int gr = lane >> 2;
    const int gc = lane & 3;

    const uint32_t sbase = smem_u32(sm);
    const int ldr = t >> 3;
    const int ldc4 = (t & 7) * 4;

    const uint32_t aOff = (uint32_t)((wm + (lane & 15)) * SROW + ((lane & 16) >> 2));
    const uint32_t bOff = (uint32_t)((wn + (lane & 7) + ((lane & 16) >> 1)) * SROW
                                     + ((lane & 8) >> 1));

    const int nk = K / 32;

    auto issue_tile = [&](int kb, int buf) {
        const int k0 = kb * 32;
        {
            const float* src = A + (size_t)(m0 + ldr) * lda + k0 + ldc4;
            uint32_t dst = sbase + (uint32_t)(buf * 2 * TILE_F) * 4u
                         + (uint32_t)(ldr * SROW + ldc4) * 4u;
#pragma unroll
            for (int i = 0; i < 4; i++)
                CP_ASYNC16(dst + (uint32_t)(i * 32 * SROW) * 4u,
                           src + (size_t)(i * 32) * lda);
        }
        {
            const float* Bp; int ldb, kk, bT;
            if (k0 < ksplit) { Bp = B1;  ldb = ldb1; kk = k0;          bT = bT1; }
            else             { Bp = B2p; ldb = ldb2; kk = k0 - ksplit; bT = bT2; }
            uint32_t bbase = sbase + (uint32_t)((buf * 2 + 1) * TILE_F) * 4u;
            if (bT) {
                const int r  = t >> 5;
                const int c4 = (t & 31) * 4;
                const float* src = Bp + (size_t)(kk + r) * ldb + n0 + c4;
#pragma unroll
                for (int i = 0; i < 4; i++)
                    CP_ASYNC16(bbase + (uint32_t)((r + i * 8) * BTS + c4) * 4u,
                               src + (size_t)(i * 8) * ldb);
            } else {
                const float* src = Bp + (size_t)(n0 + ldr) * ldb + kk + ldc4;
                uint32_t dst = bbase + (uint32_t)(ldr * SROW + ldc4) * 4u;
#pragma unroll
                for (int i = 0; i < 4; i++)
                    CP_ASYNC16(dst + (uint32_t)(i * 32 * SROW) * 4u,
                               src + (size_t)(i * 32) * ldb);
            }
        }
        CP_COMMIT();
    };

    float acc[2][8][4];
#pragma unroll
    for (int mf = 0; mf < 2; mf++)
#pragma unroll
        for (int nf = 0; nf < 8; nf++)
#pragma unroll
            for (int j = 0; j < 4; j++) acc[mf][nf][j] = 0.f;

    issue_tile(0, 0);

    for (int kb = 0; kb < nk; kb++) {
        const int buf = kb & 1;
        if (kb + 1 < nk) { issue_tile(kb + 1, buf ^ 1); CP_WAIT(1); }
        else             { CP_WAIT(0); }
        __syncthreads();

        const uint32_t sAu = sbase + (uint32_t)(buf * 2 * TILE_F) * 4u;
        const uint32_t sBu = sAu + (uint32_t)TILE_F * 4u;
        const float* sB = sm + (buf * 2 + 1) * TILE_F;
        const int modeT = (kb * 32 < ksplit) ? bT1 : bT2;

#pragma unroll
        for (int ks = 0; ks < 4; ks++) {
            const int k0 = ks * 8;
            uint32_t afr[2][4];
#pragma unroll
            for (int mf = 0; mf < 2; mf++) {
                ldsm_x4(afr[mf], sAu + (aOff + (uint32_t)(mf * 16 * SROW + k0)) * 4u);
#pragma unroll
                for (int j = 0; j < 4; j++) afr[mf][j] = tf32r_r(afr[mf][j]);
            }
            if (modeT) {
                uint32_t bfr[8][2];
#pragma unroll
                for (int nf = 0; nf < 8; nf++) {
                    const int nn = wn + nf * 8 + gr;
                    bfr[nf][0] = tf32r_u(sB[(k0 + gc) * BTS + nn]);
                    bfr[nf][1] = tf32r_u(sB[(k0 + gc + 4) * BTS + nn]);
                }
#pragma unroll
                for (int mf = 0; mf < 2; mf++)
#pragma unroll
                    for (int nf = 0; nf < 8; nf++)
                        mma_tf32(acc[mf][nf], afr[mf], bfr[nf]);
            } else {
                uint32_t bfr[4][4];
#pragma unroll
                for (int nfp = 0; nfp < 4; nfp++)
                    ldsm_x4(bfr[nfp], sBu + (bOff + (uint32_t)(nfp * 16 * SROW + k0)) * 4u);
#pragma unroll
                for (int mf = 0; mf < 2; mf++)
#pragma unroll
                    for (int nfp = 0; nfp < 4; nfp++) {
                        mma_tf32(acc[mf][nfp * 2],     afr[mf], bfr[nfp]);
                        mma_tf32(acc[mf][nfp * 2 + 1], afr[mf], bfr[nfp] + 2);
                    }
            }
        }
        __syncthreads();
    }

#pragma unroll
    for (int mf = 0; mf < 2; mf++) {
        const int m = m0 + wm + mf * 16 + gr;
        const float bi0 = bias ? bias[m]     : 0.f;
        const float bi1 = bias ? bias[m + 8] : 0.f;
#pragma unroll
        for (int nf = 0; nf < 8; nf++) {
            const int n = n0 + wn + nf * 8 + gc * 2;
            float2 r0, r1;
            r0.x = acc[mf][nf][0] + bi0; r0.y = acc[mf][nf][1] + bi0;
            r1.x = acc[mf][nf][2] + bi1; r1.y = acc[mf][nf][3] + bi1;
            if (out_mode == 2) {
                __half* Ch = (__half*)C + (size_t)b * sCb;
                *(uint32_t*)&Ch[(size_t)m * ldc + n]       = h2_rn(r0.y, r0.x);
                *(uint32_t*)&Ch[(size_t)(m + 8) * ldc + n] = h2_rn(r1.y, r1.x);
            } else {
                float* Cf = C + (size_t)b * sCb;
                if (out_mode == 1) {
                    r0.x = tf32r(r0.x); r0.y = tf32r(r0.y);
                    r1.x = tf32r(r1.x); r1.y = tf32r(r1.y);
                }
                *(float2*)&Cf[(size_t)m * ldc + n]       = r0;
                *(float2*)&Cf[(size_t)(m + 8) * ldc + n] = r1;
            }
        }
    }
}

// ---------------- fused attention: tf32 S, fp16 P.V, pipelined ----------------
// grid (32, 1, 4), 512 threads (16 warps: 4 wm x 4 qn). m-tile 128, n-tile 64.
// P = 2^(S-4) in fp16 (scale cancels in normalization; avoids fp16 overflow).
// Byte offsets in dynamic smem:
#define OP1B 0u          // P buf1: 128 rows x 144 B = 18432 (Q staging overlays)
#define OP0B 18432u      // P buf0: 18432
#define OKB_ 36864u      // K: 2 x 64 x 144 B = 18432
#define OVB_ 55296u      // V: 2 x 256 x 144 B = 73728 (fp16 rows: 64h + pad -> 144B)
#define OSUMB 129024u    // 512 floats
#define SMB_BYTES 131072

__global__ void __launch_bounds__(512) attn_pv(
    const float* __restrict__ q, const float* __restrict__ k,
    const __half* __restrict__ v, float* __restrict__ o)
{
    extern __shared__ char smc[];
    float* sQ = (float*)(smc + OP1B);        // staging only (overlaid by sP1)
    float* sSum = (float*)(smc + OSUMB);

    const int b  = blockIdx.z;
    const int m0 = blockIdx.x * 128;
    const float* qb = q + (size_t)b * NNp * CQK + (size_t)m0 * CQK;
    const float* kb = k + (size_t)b * NNp * CQK;
    const __half* vb = v + (size_t)b * CC * NNp;

    const int t = threadIdx.x;
    const int lane = t & 31, warp = t >> 5;
    const int wm = warp & 3;
    const int qn = warp >> 2;
    const int gr = lane >> 2, gc = lane & 3;

    const uint32_t sbase = smem_u32(smc);
    const uint32_t sQb = sbase + OP1B;
    const uint32_t sKb = sbase + OKB_;
    const uint32_t sVb = sbase + OVB_;
    const uint32_t sP0u = sbase + OP0B;
    const uint32_t sP1u = sbase + OP1B;

    // K (tf32 B-frag LDSM, stride 36 floats = 144B)
    const uint32_t kOff = (uint32_t)((qn * 16 + (lane & 7) + ((lane & 16) >> 1)) * 144
                                     + ((lane & 8) << 1));
    // P (fp16 A m16k16): rows (lane&15), +16B for k8..15 group
    const uint32_t pOff = (uint32_t)((lane & 15) * 144 + ((lane & 16) >> 4) * 16);
    // V (fp16 B k16n8 pairs): rows qn*64 + (lane&7) + ((lane&16)>>1), +16B if lane&8
    const uint32_t vOff = (uint32_t)((qn * 64 + (lane & 7) + ((lane & 16) >> 1)) * 144
                                     + ((lane & 8) << 1));

    // ---- prologue: Q, K(0), K(1), V(0) ----
#pragma unroll
    for (int i = 0; i < 2; i++) {
        int idx = t + i * 512;
        int r = idx >> 3, c4 = (idx & 7) * 4;
        CP_ASYNC16(sQb + (uint32_t)(r * 36 + c4) * 4u, qb + (size_t)r * CQK + c4);
    }
    {
        int r = t >> 3, c4 = (t & 7) * 4;
        CP_ASYNC16(sKb + (uint32_t)(r * 144 + c4 * 4), kb + (size_t)r * CQK + c4);
        CP_ASYNC16(sKb + (uint32_t)(64 * 144 + r * 144 + c4 * 4),
                   kb + (size_t)(64 + r) * CQK + c4);
    }
#pragma unroll
    for (int i = 0; i < 4; i++) {          // V: 256 rows x 64 halves = 2048 chunks
        int idx = t + i * 512;
        int r = idx >> 3, c8 = (idx & 7);
        CP_ASYNC16(sVb + (uint32_t)(r * 144 + c8 * 16), vb + (size_t)r * NNp + c8 * 8);
    }
    CP_COMMIT(); CP_WAIT(0); __syncthreads();

    // hoist Q fragments (frees sQ region for sP1)
    uint32_t afrQ[2][4][4];
#pragma unroll
    for (int mf = 0; mf < 2; mf++)
#pragma unroll
        for (int ks = 0; ks < 4; ks++)
            lda_frag(afrQ[mf][ks], sQ + (wm * 32 + mf * 16 + gr) * 36 + ks * 8 + gc, 36);
    __syncthreads();

    float O[2][8][4];
#pragma unroll
    for (int mf = 0; mf < 2; mf++)
#pragma unroll
        for (int cf = 0; cf < 8; cf++)
#pragma unroll
            for (int j = 0; j < 4; j++) O[mf][cf][j] = 0.f;

    float rsum[2][2] = {{0.f, 0.f}, {0.f, 0.f}};

    // S(0) -> P(0) fp16 into sP0
    {
        float sacc[2][2][4];
#pragma unroll
        for (int mf = 0; mf < 2; mf++)
#pragma unroll
            for (int nf = 0; nf < 2; nf++)
#pragma unroll
                for (int j = 0; j < 4; j++) sacc[mf][nf][j] = 0.f;
#pragma unroll
        for (int ks = 0; ks < 4; ks++) {
            uint32_t bfr[4];
            ldsm_x4(bfr, sKb + kOff + (uint32_t)(ks * 32));
#pragma unroll
            for (int mf = 0; mf < 2; mf++) {
                mma_tf32(sacc[mf][0], afrQ[mf][ks], bfr);
                mma_tf32(sacc[mf][1], afrQ[mf][ks], bfr + 2);
            }
        }
#pragma unroll
        for (int mf = 0; mf < 2; mf++)
#pragma unroll
            for (int half = 0; half < 2; half++) {
                const int row = wm * 32 + mf * 16 + half * 8 + gr;
#pragma unroll
                for (int nf = 0; nf < 2; nf++) {
                    float p0 = ex2f(sacc[mf][nf][half * 2]     - 4.f);
                    float p1 = ex2f(sacc[mf][nf][half * 2 + 1] - 4.f);
                    rsum[mf][half] += p0 + p1;
                    *(uint32_t*)(smc + OP0B + row * 144
                                 + (qn * 16 + nf * 8 + 2 * gc) * 2) = h2_rn(p1, p0);
                }
            }
    }
    __syncthreads();

    // ---- main loop: 1 sync per iteration ----
    for (int it = 0; it < 64; it++) {
        const int buf = it & 1;
        const uint32_t sPrd = (buf ? sP1u : sP0u) + (uint32_t)(wm * 32) * 144u + pOff;
        const uint32_t sVbase = sVb + (uint32_t)(buf * 36864) + vOff;

        // 0. prefetch K(it+2), V(it+1)
        if (it + 1 < 64) {
            if (it + 2 < 64) {
                const float* src = kb + (size_t)(it + 2) * 64 * CQK;
                int r = t >> 3, c4 = (t & 7) * 4;
                CP_ASYNC16(sKb + (uint32_t)(buf * 64 * 144 + r * 144 + c4 * 4),
                           src + (size_t)r * CQK + c4);
            }
            {
                const __half* src = vb + (size_t)(it + 1) * 64;
                uint32_t dstb = sVb + (uint32_t)((buf ^ 1) * 36864);
#pragma unroll
                for (int i = 0; i < 4; i++) {
                    int idx = t + i * 512;
                    int r = idx >> 3, c8 = (idx & 7);
                    CP_ASYNC16(dstb + (uint32_t)(r * 144 + c8 * 16),
                               src + (size_t)r * NNp + c8 * 8);
                }
            }
            CP_COMMIT();
        }

        // 1-2. S(it+1); ex2 -> fp16 P into sP[buf^1]
        if (it + 1 < 64) {
            const uint32_t sKbase = sKb + (uint32_t)(((it + 1) & 1) * 64 * 144) + kOff;
            float sacc[2][2][4];
#pragma unroll
            for (int mf = 0; mf < 2; mf++)
#pragma unroll
                for (int nf = 0; nf < 2; nf++)
#pragma unroll
                    for (int j = 0; j < 4; j++) sacc[mf][nf][j] = 0.f;
#pragma unroll
            for (int ks = 0; ks < 4; ks++) {
                uint32_t bfr[4];
                ldsm_x4(bfr, sKbase + (uint32_t)(ks * 32));
#pragma unroll
                for (int mf = 0; mf < 2; mf++) {
                    mma_tf32(sacc[mf][0], afrQ[mf][ks], bfr);
                    mma_tf32(sacc[mf][1], afrQ[mf][ks], bfr + 2);
                }
            }
            const uint32_t wrB = (buf ? OP0B : OP1B);
#pragma unroll
            for (int mf = 0; mf < 2; mf++)
#pragma unroll
                for (int half = 0; half < 2; half++) {
                    const int row = wm * 32 + mf * 16 + half * 8 + gr;
#pragma unroll
                    for (int nf = 0; nf < 2; nf++) {
                        float p0 = ex2f(sacc[mf][nf][half * 2]     - 4.f);
                        float p1 = ex2f(sacc[mf][nf][half * 2 + 1] - 4.f);
                        rsum[mf][half] += p0 + p1;
                        *(uint32_t*)(smc + wrB + row * 144
                                     + (qn * 16 + nf * 8 + 2 * gc) * 2) = h2_rn(p1, p0);
                    }
                }
        }

        // 3. PV(it): fp16 mma m16n8k16, 4 k-chunks of 16
#pragma unroll
        for (int ks = 0; ks < 4; ks++) {
            uint32_t afr[2][4], bfr[4][4];
            ldsm_x4(afr[0], sPrd + (uint32_t)(ks * 32));
            ldsm_x4(afr[1], sPrd + (uint32_t)(16 * 144 + ks * 32));
#pragma unroll
            for (int cfp = 0; cfp < 4; cfp++)
                ldsm_x4(bfr[cfp], sVbase + (uint32_t)(cfp * 16 * 144 + ks * 32));
#pragma unroll
            for (int mf = 0; mf < 2; mf++)
#pragma unroll
                for (int cfp = 0; cfp < 4; cfp++) {
                    mma_f16(O[mf][cfp * 2],     afr[mf], bfr[cfp]);
                    mma_f16(O[mf][cfp * 2 + 1], afr[mf], bfr[cfp] + 2);
                }
        }

        if (it + 1 < 64) { CP_WAIT(0); }
        __syncthreads();
    }

    // row-sum reduction across quadrants
#pragma unroll
    for (int mf = 0; mf < 2; mf++)
#pragma unroll
        for (int half = 0; half < 2; half++) {
            float r = rsum[mf][half];
            r += __shfl_xor_sync(0xffffffffu, r, 1);
            r += __shfl_xor_sync(0xffffffffu, r, 2);
            if (gc == 0)
                sSum[(wm * 32 + mf * 16 + half * 8 + gr) * 4 + qn] = r;
        }
    __syncthreads();

    // epilogue: normalize + write O (tf32-rounded)
    float* ob = o + (size_t)b * NNp * CC + (size_t)m0 * CC;
#pragma unroll
    for (int mf = 0; mf < 2; mf++) {
        const int r0 = wm * 32 + mf * 16 + gr;
        const int r1 = r0 + 8;
        const float inv0 = 1.f / (sSum[r0 * 4] + sSum[r0 * 4 + 1] +
                                  sSum[r0 * 4 + 2] + sSum[r0 * 4 + 3]);
        const float inv1 = 1.f / (sSum[r1 * 4] + sSum[r1 * 4 + 1] +
                                  sSum[r1 * 4 + 2] + sSum[r1 * 4 + 3]);
#pragma unroll
        for (int cf = 0; cf < 8; cf++) {
            const int c = qn * 64 + cf * 8 + gc * 2;
            *(float2*)&ob[(size_t)r0 * CC + c] =
                make_float2(tf32r(O[mf][cf][0] * inv0), tf32r(O[mf][cf][1] * inv0));
            *(float2*)&ob[(size_t)r1 * CC + c] =
                make_float2(tf32r(O[mf][cf][2] * inv1), tf32r(O[mf][cf][3] * inv1));
        }
    }
}

// ---------------- prep: qk projection only ----------------------------------
__global__ void __launch_bounds__(256) qk_prep(
    const float* __restrict__ x,
    const float* __restrict__ Wq, const float* __restrict__ bq,
    const float* __restrict__ Wk, const float* __restrict__ bk,
    float* __restrict__ q, float* __restrict__ ko)
{
    __shared__ float sbuf[6144];
    const int bid = blockIdx.x;
    const int t = threadIdx.x;

    const int m0 = (bid & 31) * 128;
    const int b  = bid >> 5;
    const float* xb = x + (size_t)b * CC * NNp;
    float (*sx)[128] = (float(*)[128])sbuf;
    float (*sw)[32]  = (float(*)[32])(sbuf + 4096);

    const int mi   = t & 127;
    const int half = t >> 7;

    float acc[32];
    const float* bias = half ? bk : bq;
#pragma unroll
    for (int j = 0; j < 32; j++) acc[j] = bias[j];

    for (int c0 = 0; c0 < CC; c0 += 32) {
#pragma unroll
        for (int i = 0; i < 16; i++) {
            int idx = t + i * 256;
            int r = idx >> 7, mm = idx & 127;
            sx[r][mm] = xb[(size_t)(c0 + r) * NNp + m0 + mm];
        }
#pragma unroll
        for (int i = 0; i < 8; i++) {
            int idx = t + i * 256;
            int co = idx >> 5, cc = idx & 31;
            sw[co][cc] = (co < 32) ? Wq[co * 256 + c0 + cc]
                                   : Wk[(co - 32) * 256 + c0 + cc];
        }
        __syncthreads();
#pragma unroll
        for (int cc = 0; cc < 32; cc++) {
            float xv = sx[cc][mi];
#pragma unroll
            for (int j = 0; j < 32; j++) acc[j] += sw[half * 32 + j][cc] * xv;
        }
        __syncthreads();
    }

    const float scl = half ? 1.f : 1.4426950408889634f;
    float* dst = (half ? ko : q) + (size_t)b * NNp * CQK + (size_t)(m0 + mi) * CQK;
#pragma unroll
    for (int j = 0; j < 32; j += 4)
        *(float4*)&dst[j] = make_float4(tf32r(acc[j] * scl), tf32r(acc[j + 1] * scl),
                                        tf32r(acc[j + 2] * scl), tf32r(acc[j + 3] * scl));
}

// ---------------- launch ----------------
extern "C" void kernel_launch(void* const* d_in, const int* in_sizes, int n_in,
                              void* d_out, int out_size)
{
    const float* x  = (const float*)d_in[0];
    const float* Wq = (const float*)d_in[1];
    const float* bq = (const float*)d_in[2];
    const float* Wk = (const float*)d_in[3];
    const float* bk = (const float*)d_in[4];
    const float* Wv = (const float*)d_in[5];
    const float* bv = (const float*)d_in[6];
    const float* Wo = (const float*)d_in[7];
    const float* bo = (const float*)d_in[8];
    float* y = (float*)d_out;

    float *p_q, *p_k, *p_o;
    __half* p_v;
    cudaGetSymbolAddress((void**)&p_q,  g_q);
    cudaGetSymbolAddress((void**)&p_k,  g_k);
    cudaGetSymbolAddress((void**)&p_v,  g_v);
    cudaGetSymbolAddress((void**)&p_o,  g_o);

    const size_t sX = (size_t)CC * NNp;

    const int SMEM_G = 4 * TILE_F * 4;
    cudaFuncSetAttribute(tc_gemm, cudaFuncAttributeMaxDynamicSharedMemorySize, SMEM_G);
    cudaFuncSetAttribute(attn_pv, cudaFuncAttributeMaxDynamicSharedMemorySize, SMB_BYTES);

    // prep: qk projection only
    qk_prep<<<128, 256>>>(x, Wq, bq, Wk, bk, p_q, p_k);

    // v[c][n] = Wv @ x + bv -> fp16 (out_mode 2); B = x transposed mode
    tc_gemm<<<dim3(NNp / 128, CC / 128, BB), 256, SMEM_G>>>(
        Wv, CC, 0,
        x, NNp, sX, 1,
        nullptr, 0, 0, 0, CC,
        (float*)p_v, NNp, sX,
        bv, CC, 2);

    // fused attention (tf32 S, fp16 PV) -> g_o [m][c]
    attn_pv<<<dim3(NNp / 128, 1, BB), 512, SMB_BYTES>>>(p_q, p_k, p_v, p_o);

    // y = Wo @ concat(o, x)^T + bo
    tc_gemm<<<dim3(NNp / 128, CC / 128, BB), 256, SMEM_G>>>(
        Wo, 2 * CC, 0,
        p_o, CC, sX, 0,
        x, NNp, sX, 1, CC,
        y, NNp, sX,
        bo, 2 * CC, 0);
}